// round 1
// baseline (speedup 1.0000x reference)
#include <cuda_runtime.h>
#include <cuda_bf16.h>
#include <cstdint>

#define NMAX 100000
#define F 128

// Scratch (device globals — no allocation allowed)
__device__ float g_deg [NMAX];
__device__ float g_dinv[NMAX];
__device__ float g_h   [(size_t)NMAX * F];  // GEMM output (h1, then h2)
__device__ float g_a   [(size_t)NMAX * F];  // layer-1 aggregation (pre-relu)
__device__ float g_a2  [(size_t)NMAX * F];  // layer-2 aggregation (pre-relu)

// ---------------------------------------------------------------------------
// degree / dinv
// ---------------------------------------------------------------------------
__global__ void k_init_deg(float* __restrict__ deg, int n) {
    int i = blockIdx.x * blockDim.x + threadIdx.x;
    if (i < n) deg[i] = 1.0f;  // self-loop contributes 1
}

__global__ void k_count_deg(const int* __restrict__ col, float* __restrict__ deg, int E) {
    int i = blockIdx.x * blockDim.x + threadIdx.x;
    if (i < E) atomicAdd(&deg[col[i]], 1.0f);
}

__global__ void k_dinv(const float* __restrict__ deg, float* __restrict__ dinv, int n) {
    int i = blockIdx.x * blockDim.x + threadIdx.x;
    if (i < n) dinv[i] = rsqrtf(deg[i]);
}

// ---------------------------------------------------------------------------
// GEMM: H = act(A) @ W  [M x 128] = [M x 128][128 x 128]
// Also initializes Aout[r][c] = bias[c] + dinv[r]^2 * H[r][c]  (self-loop term)
// Block: 256 threads, tile 64 rows x 128 cols; W fully in smem.
// ---------------------------------------------------------------------------
#define AS_LD 132  // padded leading dim (keeps 16B alignment, kills bank conflicts)

template <bool RELU_IN>
__global__ void k_gemm(const float* __restrict__ A, const float* __restrict__ W,
                       const float* __restrict__ bias, const float* __restrict__ dinv,
                       float* __restrict__ H, float* __restrict__ Aout, int M) {
    extern __shared__ float smem[];
    float* Ws = smem;            // 128*128 floats
    float* As = smem + F * F;    // 64 * AS_LD floats

    const int tid = threadIdx.x;
    const int block_row = blockIdx.x * 64;

    // Load W (64KB) cooperatively as float4
    {
        const float4* Wg = (const float4*)W;
        float4* Ws4 = (float4*)Ws;
        #pragma unroll
        for (int i = tid; i < (F * F) / 4; i += 256) Ws4[i] = Wg[i];
    }
    // Load A tile: 64 rows x 32 float4 per row
    for (int i = tid; i < 64 * 32; i += 256) {
        int r  = i >> 5;
        int c4 = i & 31;
        int gr = block_row + r;
        float4 v = make_float4(0.f, 0.f, 0.f, 0.f);
        if (gr < M) v = ((const float4*)(A + (size_t)gr * F))[c4];
        if (RELU_IN) {
            v.x = fmaxf(v.x, 0.f); v.y = fmaxf(v.y, 0.f);
            v.z = fmaxf(v.z, 0.f); v.w = fmaxf(v.w, 0.f);
        }
        *(float4*)(As + r * AS_LD + c4 * 4) = v;
    }
    __syncthreads();

    const int ty = tid >> 4;   // 0..15 -> 4 rows each
    const int tx = tid & 15;   // 0..15 -> 8 cols each

    float acc[4][8];
    #pragma unroll
    for (int i = 0; i < 4; i++)
        #pragma unroll
        for (int j = 0; j < 8; j++) acc[i][j] = 0.f;

    const float* a_base = As + (ty * 4) * AS_LD;
    const float4* w_base = (const float4*)Ws + tx * 2;

    #pragma unroll 4
    for (int k = 0; k < F; k++) {
        float a0 = a_base[0 * AS_LD + k];
        float a1 = a_base[1 * AS_LD + k];
        float a2 = a_base[2 * AS_LD + k];
        float a3 = a_base[3 * AS_LD + k];
        float4 w0 = w_base[k * 32];
        float4 w1 = w_base[k * 32 + 1];
        float wv[8] = {w0.x, w0.y, w0.z, w0.w, w1.x, w1.y, w1.z, w1.w};
        float av[4] = {a0, a1, a2, a3};
        #pragma unroll
        for (int i = 0; i < 4; i++)
            #pragma unroll
            for (int j = 0; j < 8; j++) acc[i][j] = fmaf(av[i], wv[j], acc[i][j]);
    }

    // Epilogue: write H and self-loop-initialized Aout
    #pragma unroll
    for (int i = 0; i < 4; i++) {
        int gr = block_row + ty * 4 + i;
        if (gr >= M) continue;
        float di = dinv[gr];
        float d2 = di * di;
        float* hrow = H    + (size_t)gr * F + tx * 8;
        float* arow = Aout + (size_t)gr * F + tx * 8;
        #pragma unroll
        for (int j = 0; j < 8; j += 4) {
            float4 hv = make_float4(acc[i][j], acc[i][j+1], acc[i][j+2], acc[i][j+3]);
            float4 bv = *(const float4*)(bias + tx * 8 + j);
            float4 av = make_float4(fmaf(d2, hv.x, bv.x), fmaf(d2, hv.y, bv.y),
                                    fmaf(d2, hv.z, bv.z), fmaf(d2, hv.w, bv.w));
            *(float4*)(hrow + j) = hv;
            *(float4*)(arow + j) = av;
        }
    }
}

// ---------------------------------------------------------------------------
// Edge aggregation: A[col] += H[row] * dinv[row]*dinv[col]
// Warp per edge; lane handles one float4 (32 lanes x 4 = 128 features).
// Vector reduction (red.global.add.v4.f32) — no read-back, L2-side atomics.
// ---------------------------------------------------------------------------
__global__ void k_edge_agg(const int* __restrict__ row, const int* __restrict__ col,
                           const float* __restrict__ dinv,
                           const float* __restrict__ H, float* __restrict__ Aout, int E) {
    int e = (blockIdx.x * blockDim.x + threadIdx.x) >> 5;
    int lane = threadIdx.x & 31;
    if (e >= E) return;
    int r = __ldg(row + e);
    int c = __ldg(col + e);
    float norm = __ldg(dinv + r) * __ldg(dinv + c);
    float4 v = __ldg((const float4*)(H + (size_t)r * F) + lane);
    v.x *= norm; v.y *= norm; v.z *= norm; v.w *= norm;
    float* dst = Aout + (size_t)c * F + lane * 4;
    asm volatile("red.global.add.v4.f32 [%0], {%1, %2, %3, %4};"
                 :: "l"(dst), "f"(v.x), "f"(v.y), "f"(v.z), "f"(v.w)
                 : "memory");
}

// ---------------------------------------------------------------------------
// Head: out[v] = sigmoid( dot(relu(A2[v]), Wl) + bl )
// Warp per node.
// ---------------------------------------------------------------------------
__global__ void k_head(const float* __restrict__ A2, const float* __restrict__ Wl,
                       const float* __restrict__ bl, float* __restrict__ out, int n) {
    int v = blockIdx.x * (blockDim.x >> 5) + (threadIdx.x >> 5);
    int lane = threadIdx.x & 31;
    if (v >= n) return;
    float4 a = __ldg((const float4*)(A2 + (size_t)v * F) + lane);
    float4 w = __ldg((const float4*)Wl + lane);
    float s = fmaxf(a.x, 0.f) * w.x + fmaxf(a.y, 0.f) * w.y +
              fmaxf(a.z, 0.f) * w.z + fmaxf(a.w, 0.f) * w.w;
    #pragma unroll
    for (int off = 16; off; off >>= 1) s += __shfl_xor_sync(0xFFFFFFFFu, s, off);
    if (lane == 0) {
        float z = s + __ldg(bl);
        out[v] = 1.0f / (1.0f + expf(-z));
    }
}

// ---------------------------------------------------------------------------
extern "C" void kernel_launch(void* const* d_in, const int* in_sizes, int n_in,
                              void* d_out, int out_size) {
    const float* x  = (const float*)d_in[0];
    const int*   ei = (const int*)  d_in[1];
    const float* W1 = (const float*)d_in[2];
    const float* b1 = (const float*)d_in[3];
    const float* W2 = (const float*)d_in[4];
    const float* b2 = (const float*)d_in[5];
    const float* Wl = (const float*)d_in[6];
    const float* bl = (const float*)d_in[7];

    int n = in_sizes[0] / F;        // 100000
    int E = in_sizes[1] / 2;        // 3200000
    const int* rowp = ei;
    const int* colp = ei + E;

    float *deg, *dinv, *h, *a, *a2;
    cudaGetSymbolAddress((void**)&deg,  g_deg);
    cudaGetSymbolAddress((void**)&dinv, g_dinv);
    cudaGetSymbolAddress((void**)&h,    g_h);
    cudaGetSymbolAddress((void**)&a,    g_a);
    cudaGetSymbolAddress((void**)&a2,   g_a2);

    const size_t gemm_smem = (size_t)(F * F + 64 * AS_LD) * sizeof(float); // ~99.3KB
    cudaFuncSetAttribute(k_gemm<false>, cudaFuncAttributeMaxDynamicSharedMemorySize, (int)gemm_smem);
    cudaFuncSetAttribute(k_gemm<true>,  cudaFuncAttributeMaxDynamicSharedMemorySize, (int)gemm_smem);

    // --- degree + dinv ---
    k_init_deg <<<(n + 255) / 256, 256>>>(deg, n);
    k_count_deg<<<(E + 255) / 256, 256>>>(colp, deg, E);
    k_dinv     <<<(n + 255) / 256, 256>>>(deg, dinv, n);

    int gemm_grid = (n + 63) / 64;
    long long edge_threads = (long long)E * 32;
    int edge_grid = (int)((edge_threads + 255) / 256);

    // --- layer 1: h1 = x @ W1 ; a1 = b1 + dinv^2*h1 + scatter ---
    k_gemm<false><<<gemm_grid, 256, gemm_smem>>>(x, W1, b1, dinv, h, a, n);
    k_edge_agg   <<<edge_grid, 256>>>(rowp, colp, dinv, h, a, E);

    // --- layer 2: h2 = relu(a1) @ W2 ; a2 = b2 + dinv^2*h2 + scatter ---
    k_gemm<true><<<gemm_grid, 256, gemm_smem>>>(a, W2, b2, dinv, h, a2, n);
    k_edge_agg  <<<edge_grid, 256>>>(rowp, colp, dinv, h, a2, E);

    // --- head ---
    k_head<<<(n + 7) / 8, 256>>>(a2, Wl, bl, (float*)d_out, n);
}

// round 2
// speedup vs baseline: 2.0562x; 2.0562x over previous
#include <cuda_runtime.h>
#include <cuda_bf16.h>
#include <cstdint>

#define NMAX 100000
#define EMAX 3200000
#define F 128

// Scratch (device globals — no allocation allowed)
__device__ int   g_cnt   [NMAX];
__device__ int   g_start [NMAX + 1];
__device__ int   g_cursor[NMAX];
__device__ int   g_bsum  [256];
__device__ int   g_boff  [256];
__device__ int   g_srow  [EMAX];            // edge row-ids sorted by col
__device__ float g_dinv  [NMAX];
__device__ float g_h     [(size_t)NMAX * F]; // GEMM output (h1, then h2)
__device__ float g_a     [(size_t)NMAX * F]; // layer-1 aggregated output

// ---------------------------------------------------------------------------
// degree histogram / dinv
// ---------------------------------------------------------------------------
__global__ void k_zero_cnt(int* __restrict__ cnt, int n) {
    int i = blockIdx.x * blockDim.x + threadIdx.x;
    if (i < n) cnt[i] = 0;
}

__global__ void k_hist(const int* __restrict__ col, int* __restrict__ cnt, int E) {
    int i = blockIdx.x * blockDim.x + threadIdx.x;
    if (i < E) atomicAdd(&cnt[col[i]], 1);
}

__global__ void k_dinv(const int* __restrict__ cnt, float* __restrict__ dinv, int n) {
    int i = blockIdx.x * blockDim.x + threadIdx.x;
    if (i < n) dinv[i] = rsqrtf((float)(cnt[i] + 1));  // +1 self-loop
}

// ---------------------------------------------------------------------------
// Counting sort of edges by col: scan of cnt -> start, then scatter row ids.
// ---------------------------------------------------------------------------
#define SCAN_BLK 1024  // elements per block (256 threads x 4)

__global__ void k_blocksum(const int* __restrict__ cnt, int* __restrict__ bsum, int n) {
    __shared__ int sm[256];
    int t = threadIdx.x, b = blockIdx.x;
    int base = b * SCAN_BLK;
    int s = 0;
    #pragma unroll
    for (int k = 0; k < 4; k++) {
        int i = base + t * 4 + k;
        if (i < n) s += cnt[i];
    }
    sm[t] = s; __syncthreads();
    for (int off = 128; off > 0; off >>= 1) {
        if (t < off) sm[t] += sm[t + off];
        __syncthreads();
    }
    if (t == 0) bsum[b] = sm[0];
}

__global__ void k_scanbsum(const int* __restrict__ bsum, int* __restrict__ boff,
                           int* __restrict__ start, int nb, int n) {
    __shared__ int sm[256];
    int t = threadIdx.x;
    int v = (t < nb) ? bsum[t] : 0;
    sm[t] = v; __syncthreads();
    #pragma unroll
    for (int off = 1; off < 256; off <<= 1) {
        int x = 0;
        if (t >= off) x = sm[t - off];
        __syncthreads();
        sm[t] += x;
        __syncthreads();
    }
    if (t < nb) boff[t] = sm[t] - v;        // exclusive
    if (t == 255) start[n] = sm[255];       // total = E
}

__global__ void k_writestart(const int* __restrict__ cnt, const int* __restrict__ boff,
                             int* __restrict__ start, int* __restrict__ cursor, int n) {
    __shared__ int sm[256];
    int t = threadIdx.x, b = blockIdx.x;
    int base = b * SCAN_BLK + t * 4;
    int c[4]; int s = 0;
    #pragma unroll
    for (int k = 0; k < 4; k++) {
        c[k] = (base + k < n) ? cnt[base + k] : 0;
        s += c[k];
    }
    sm[t] = s; __syncthreads();
    #pragma unroll
    for (int off = 1; off < 256; off <<= 1) {
        int x = 0;
        if (t >= off) x = sm[t - off];
        __syncthreads();
        sm[t] += x;
        __syncthreads();
    }
    int excl = boff[b] + sm[t] - s;
    #pragma unroll
    for (int k = 0; k < 4; k++) {
        int i = base + k;
        if (i < n) { start[i] = excl; cursor[i] = excl; }
        excl += c[k];
    }
}

__global__ void k_scatter(const int* __restrict__ row, const int* __restrict__ col,
                          int* __restrict__ cursor, int* __restrict__ srow, int E) {
    int i = blockIdx.x * blockDim.x + threadIdx.x;
    if (i >= E) return;
    int c = col[i];
    int pos = atomicAdd(&cursor[c], 1);
    srow[pos] = row[i];
}

// ---------------------------------------------------------------------------
// GEMM: H = act(A) @ W  [M x 128] = [M x 128][128 x 128], W in smem.
// ---------------------------------------------------------------------------
#define AS_LD 132

template <bool RELU_IN>
__global__ void k_gemm(const float* __restrict__ A, const float* __restrict__ W,
                       float* __restrict__ H, int M) {
    extern __shared__ float smem[];
    float* Ws = smem;            // 128*128
    float* As = smem + F * F;    // 64 * AS_LD

    const int tid = threadIdx.x;
    const int block_row = blockIdx.x * 64;

    {
        const float4* Wg = (const float4*)W;
        float4* Ws4 = (float4*)Ws;
        #pragma unroll
        for (int i = tid; i < (F * F) / 4; i += 256) Ws4[i] = Wg[i];
    }
    for (int i = tid; i < 64 * 32; i += 256) {
        int r  = i >> 5;
        int c4 = i & 31;
        int gr = block_row + r;
        float4 v = make_float4(0.f, 0.f, 0.f, 0.f);
        if (gr < M) v = ((const float4*)(A + (size_t)gr * F))[c4];
        if (RELU_IN) {
            v.x = fmaxf(v.x, 0.f); v.y = fmaxf(v.y, 0.f);
            v.z = fmaxf(v.z, 0.f); v.w = fmaxf(v.w, 0.f);
        }
        *(float4*)(As + r * AS_LD + c4 * 4) = v;
    }
    __syncthreads();

    const int ty = tid >> 4;   // 0..15 -> 4 rows
    const int tx = tid & 15;   // 0..15 -> 8 cols

    float acc[4][8];
    #pragma unroll
    for (int i = 0; i < 4; i++)
        #pragma unroll
        for (int j = 0; j < 8; j++) acc[i][j] = 0.f;

    const float* a_base = As + (ty * 4) * AS_LD;
    const float4* w_base = (const float4*)Ws + tx * 2;

    #pragma unroll 4
    for (int k = 0; k < F; k++) {
        float av[4];
        #pragma unroll
        for (int i = 0; i < 4; i++) av[i] = a_base[i * AS_LD + k];
        float4 w0 = w_base[k * 32];
        float4 w1 = w_base[k * 32 + 1];
        float wv[8] = {w0.x, w0.y, w0.z, w0.w, w1.x, w1.y, w1.z, w1.w};
        #pragma unroll
        for (int i = 0; i < 4; i++)
            #pragma unroll
            for (int j = 0; j < 8; j++) acc[i][j] = fmaf(av[i], wv[j], acc[i][j]);
    }

    #pragma unroll
    for (int i = 0; i < 4; i++) {
        int gr = block_row + ty * 4 + i;
        if (gr >= M) continue;
        float* hrow = H + (size_t)gr * F + tx * 8;
        #pragma unroll
        for (int j = 0; j < 8; j += 4)
            *(float4*)(hrow + j) = make_float4(acc[i][j], acc[i][j+1],
                                               acc[i][j+2], acc[i][j+3]);
    }
}

// ---------------------------------------------------------------------------
// Gather aggregation: warp per node.
//   a[c] = bias + dinv[c]^2 * H[c] + sum_{r in N(c)} dinv[r]*dinv[c] * H[r]
// FUSE_HEAD: instead of writing the row, compute sigmoid(dot(relu(row), Wl)+bl).
// ---------------------------------------------------------------------------
template <bool FUSE_HEAD>
__global__ void k_agg(const int* __restrict__ start, const int* __restrict__ srow,
                      const float* __restrict__ dinv, const float* __restrict__ H,
                      const float* __restrict__ bias,
                      const float* __restrict__ Wl, const float* __restrict__ bl,
                      float* __restrict__ out, int n) {
    int c = blockIdx.x * (blockDim.x >> 5) + (threadIdx.x >> 5);
    int lane = threadIdx.x & 31;
    if (c >= n) return;

    float dc = __ldg(dinv + c);
    int beg = __ldg(start + c);
    int end = __ldg(start + c + 1);

    // self-loop term
    float4 hv = __ldg((const float4*)(H + (size_t)c * F) + lane);
    float d2 = dc * dc;
    float4 acc = make_float4(hv.x * d2, hv.y * d2, hv.z * d2, hv.w * d2);

    int i = beg;
    for (; i + 1 < end; i += 2) {
        int r0 = __ldg(srow + i);
        int r1 = __ldg(srow + i + 1);
        float n0 = __ldg(dinv + r0) * dc;
        float n1 = __ldg(dinv + r1) * dc;
        float4 v0 = __ldg((const float4*)(H + (size_t)r0 * F) + lane);
        float4 v1 = __ldg((const float4*)(H + (size_t)r1 * F) + lane);
        acc.x = fmaf(v0.x, n0, acc.x); acc.y = fmaf(v0.y, n0, acc.y);
        acc.z = fmaf(v0.z, n0, acc.z); acc.w = fmaf(v0.w, n0, acc.w);
        acc.x = fmaf(v1.x, n1, acc.x); acc.y = fmaf(v1.y, n1, acc.y);
        acc.z = fmaf(v1.z, n1, acc.z); acc.w = fmaf(v1.w, n1, acc.w);
    }
    if (i < end) {
        int r0 = __ldg(srow + i);
        float n0 = __ldg(dinv + r0) * dc;
        float4 v0 = __ldg((const float4*)(H + (size_t)r0 * F) + lane);
        acc.x = fmaf(v0.x, n0, acc.x); acc.y = fmaf(v0.y, n0, acc.y);
        acc.z = fmaf(v0.z, n0, acc.z); acc.w = fmaf(v0.w, n0, acc.w);
    }

    float4 bv = __ldg((const float4*)bias + lane);
    acc.x += bv.x; acc.y += bv.y; acc.z += bv.z; acc.w += bv.w;

    if (!FUSE_HEAD) {
        *(float4*)(out + (size_t)c * F + lane * 4) = acc;
    } else {
        float4 w = __ldg((const float4*)Wl + lane);
        float s = fmaxf(acc.x, 0.f) * w.x + fmaxf(acc.y, 0.f) * w.y +
                  fmaxf(acc.z, 0.f) * w.z + fmaxf(acc.w, 0.f) * w.w;
        #pragma unroll
        for (int off = 16; off; off >>= 1) s += __shfl_xor_sync(0xFFFFFFFFu, s, off);
        if (lane == 0) {
            float z = s + __ldg(bl);
            out[c] = 1.0f / (1.0f + expf(-z));
        }
    }
}

// ---------------------------------------------------------------------------
extern "C" void kernel_launch(void* const* d_in, const int* in_sizes, int n_in,
                              void* d_out, int out_size) {
    const float* x  = (const float*)d_in[0];
    const int*   ei = (const int*)  d_in[1];
    const float* W1 = (const float*)d_in[2];
    const float* b1 = (const float*)d_in[3];
    const float* W2 = (const float*)d_in[4];
    const float* b2 = (const float*)d_in[5];
    const float* Wl = (const float*)d_in[6];
    const float* bl = (const float*)d_in[7];

    int n = in_sizes[0] / F;
    int E = in_sizes[1] / 2;
    const int* rowp = ei;
    const int* colp = ei + E;

    int *cnt, *start, *cursor, *bsum, *boff, *srow;
    float *dinv, *h, *a;
    cudaGetSymbolAddress((void**)&cnt,    g_cnt);
    cudaGetSymbolAddress((void**)&start,  g_start);
    cudaGetSymbolAddress((void**)&cursor, g_cursor);
    cudaGetSymbolAddress((void**)&bsum,   g_bsum);
    cudaGetSymbolAddress((void**)&boff,   g_boff);
    cudaGetSymbolAddress((void**)&srow,   g_srow);
    cudaGetSymbolAddress((void**)&dinv,   g_dinv);
    cudaGetSymbolAddress((void**)&h,      g_h);
    cudaGetSymbolAddress((void**)&a,      g_a);

    const size_t gemm_smem = (size_t)(F * F + 64 * AS_LD) * sizeof(float);
    cudaFuncSetAttribute(k_gemm<false>, cudaFuncAttributeMaxDynamicSharedMemorySize, (int)gemm_smem);
    cudaFuncSetAttribute(k_gemm<true>,  cudaFuncAttributeMaxDynamicSharedMemorySize, (int)gemm_smem);
    cudaFuncSetAttribute(k_gemm<false>, cudaFuncAttributePreferredSharedMemoryCarveout, 100);
    cudaFuncSetAttribute(k_gemm<true>,  cudaFuncAttributePreferredSharedMemoryCarveout, 100);

    int nb = (n + SCAN_BLK - 1) / SCAN_BLK;  // <= 98

    // --- degree + counting sort prep ---
    k_zero_cnt<<<(n + 255) / 256, 256>>>(cnt, n);
    k_hist    <<<(E + 255) / 256, 256>>>(colp, cnt, E);
    k_dinv    <<<(n + 255) / 256, 256>>>(cnt, dinv, n);
    k_blocksum<<<nb, 256>>>(cnt, bsum, n);
    k_scanbsum<<<1, 256>>>(bsum, boff, start, nb, n);
    k_writestart<<<nb, 256>>>(cnt, boff, start, cursor, n);
    k_scatter <<<(E + 255) / 256, 256>>>(rowp, colp, cursor, srow, E);

    int gemm_grid = (n + 63) / 64;
    int agg_grid  = (n * 32 + 255) / 256;

    // --- layer 1 ---
    k_gemm<false><<<gemm_grid, 256, gemm_smem>>>(x, W1, h, n);
    k_agg<false> <<<agg_grid, 256>>>(start, srow, dinv, h, b1, nullptr, nullptr, a, n);

    // --- layer 2 + fused head ---
    k_gemm<true><<<gemm_grid, 256, gemm_smem>>>(a, W2, h, n);
    k_agg<true> <<<agg_grid, 256>>>(start, srow, dinv, h, b2, Wl, bl, (float*)d_out, n);
}

// round 3
// speedup vs baseline: 2.4496x; 1.1913x over previous
#include <cuda_runtime.h>
#include <cuda_fp16.h>
#include <cstdint>

#define NMAX 100000
#define EMAX 3200000
#define F 128

// Scratch (device globals — no allocation allowed)
__device__ int    g_cnt   [NMAX];
__device__ int    g_start [NMAX + 1];
__device__ int    g_cursor[NMAX];
__device__ int    g_bsum  [256];
__device__ int    g_boff  [256];
__device__ int    g_srow  [EMAX];             // edge row-ids sorted by col
__device__ float  g_dinv  [NMAX];
__device__ __half g_h     [(size_t)NMAX * F]; // GEMM output (fp16)
__device__ float  g_a     [(size_t)NMAX * F]; // layer-1 aggregated output (fp32)

// ---------------------------------------------------------------------------
// degree histogram / dinv
// ---------------------------------------------------------------------------
__global__ void k_zero_cnt(int* __restrict__ cnt, int n) {
    int i = blockIdx.x * blockDim.x + threadIdx.x;
    if (i < n) cnt[i] = 0;
}

__global__ void k_hist(const int* __restrict__ col, int* __restrict__ cnt, int E) {
    int i = blockIdx.x * blockDim.x + threadIdx.x;
    if (i < E) atomicAdd(&cnt[col[i]], 1);
}

__global__ void k_dinv(const int* __restrict__ cnt, float* __restrict__ dinv, int n) {
    int i = blockIdx.x * blockDim.x + threadIdx.x;
    if (i < n) dinv[i] = rsqrtf((float)(cnt[i] + 1));  // +1 self-loop
}

// ---------------------------------------------------------------------------
// Counting sort of edges by col
// ---------------------------------------------------------------------------
#define SCAN_BLK 1024

__global__ void k_blocksum(const int* __restrict__ cnt, int* __restrict__ bsum, int n) {
    __shared__ int sm[256];
    int t = threadIdx.x, b = blockIdx.x;
    int base = b * SCAN_BLK;
    int s = 0;
    #pragma unroll
    for (int k = 0; k < 4; k++) {
        int i = base + t * 4 + k;
        if (i < n) s += cnt[i];
    }
    sm[t] = s; __syncthreads();
    for (int off = 128; off > 0; off >>= 1) {
        if (t < off) sm[t] += sm[t + off];
        __syncthreads();
    }
    if (t == 0) bsum[b] = sm[0];
}

__global__ void k_scanbsum(const int* __restrict__ bsum, int* __restrict__ boff,
                           int* __restrict__ start, int nb, int n) {
    __shared__ int sm[256];
    int t = threadIdx.x;
    int v = (t < nb) ? bsum[t] : 0;
    sm[t] = v; __syncthreads();
    #pragma unroll
    for (int off = 1; off < 256; off <<= 1) {
        int x = 0;
        if (t >= off) x = sm[t - off];
        __syncthreads();
        sm[t] += x;
        __syncthreads();
    }
    if (t < nb) boff[t] = sm[t] - v;
    if (t == 255) start[n] = sm[255];
}

__global__ void k_writestart(const int* __restrict__ cnt, const int* __restrict__ boff,
                             int* __restrict__ start, int* __restrict__ cursor, int n) {
    __shared__ int sm[256];
    int t = threadIdx.x, b = blockIdx.x;
    int base = b * SCAN_BLK + t * 4;
    int c[4]; int s = 0;
    #pragma unroll
    for (int k = 0; k < 4; k++) {
        c[k] = (base + k < n) ? cnt[base + k] : 0;
        s += c[k];
    }
    sm[t] = s; __syncthreads();
    #pragma unroll
    for (int off = 1; off < 256; off <<= 1) {
        int x = 0;
        if (t >= off) x = sm[t - off];
        __syncthreads();
        sm[t] += x;
        __syncthreads();
    }
    int excl = boff[b] + sm[t] - s;
    #pragma unroll
    for (int k = 0; k < 4; k++) {
        int i = base + k;
        if (i < n) { start[i] = excl; cursor[i] = excl; }
        excl += c[k];
    }
}

__global__ void k_scatter(const int* __restrict__ row, const int* __restrict__ col,
                          int* __restrict__ cursor, int* __restrict__ srow, int E) {
    int i = blockIdx.x * blockDim.x + threadIdx.x;
    if (i >= E) return;
    int c = col[i];
    int pos = atomicAdd(&cursor[c], 1);
    srow[pos] = row[i];
}

// ---------------------------------------------------------------------------
// GEMM: H(fp16) = act(A) @ W.   W in smem (64KB); A streamed via L1 broadcast.
// 256 threads, 64 rows/CTA; thread = 4 rows x 8 cols. 3 CTAs/SM.
// ---------------------------------------------------------------------------
template <bool RELU_IN>
__global__ void __launch_bounds__(256, 3)
k_gemm(const float* __restrict__ A, const float* __restrict__ W,
       __half* __restrict__ H, int M) {
    extern __shared__ float Ws[];  // 128x128
    const int tid = threadIdx.x;
    const int ty = tid >> 4;   // 0..15 -> 4 rows each
    const int tx = tid & 15;   // 0..15 -> 8 cols each
    const int block_row = blockIdx.x * 64;

    {
        const float4* Wg = (const float4*)W;
        float4* Ws4 = (float4*)Ws;
        #pragma unroll
        for (int i = tid; i < (F * F) / 4; i += 256) Ws4[i] = Wg[i];
    }
    __syncthreads();

    const int r0 = block_row + ty * 4;
    const float4* Arow[4];
    #pragma unroll
    for (int i = 0; i < 4; i++) {
        int r = min(r0 + i, M - 1);
        Arow[i] = (const float4*)(A + (size_t)r * F);
    }

    float acc[4][8];
    #pragma unroll
    for (int i = 0; i < 4; i++)
        #pragma unroll
        for (int j = 0; j < 8; j++) acc[i][j] = 0.f;

    #pragma unroll 2
    for (int k4 = 0; k4 < F / 4; k4++) {
        float4 av4[4];
        #pragma unroll
        for (int i = 0; i < 4; i++) {
            float4 v = __ldg(Arow[i] + k4);   // broadcast across 16 lanes
            if (RELU_IN) {
                v.x = fmaxf(v.x, 0.f); v.y = fmaxf(v.y, 0.f);
                v.z = fmaxf(v.z, 0.f); v.w = fmaxf(v.w, 0.f);
            }
            av4[i] = v;
        }
        #pragma unroll
        for (int kk = 0; kk < 4; kk++) {
            int k = k4 * 4 + kk;
            float4 w0 = *(const float4*)(Ws + k * F + tx * 8);
            float4 w1 = *(const float4*)(Ws + k * F + tx * 8 + 4);
            float wv[8] = {w0.x, w0.y, w0.z, w0.w, w1.x, w1.y, w1.z, w1.w};
            #pragma unroll
            for (int i = 0; i < 4; i++) {
                float a = ((const float*)&av4[i])[kk];
                #pragma unroll
                for (int j = 0; j < 8; j++) acc[i][j] = fmaf(a, wv[j], acc[i][j]);
            }
        }
    }

    #pragma unroll
    for (int i = 0; i < 4; i++) {
        int gr = r0 + i;
        if (gr >= M) continue;
        __half2 hv[4];
        #pragma unroll
        for (int j2 = 0; j2 < 4; j2++)
            hv[j2] = __float22half2_rn(make_float2(acc[i][2*j2], acc[i][2*j2+1]));
        *(uint4*)(H + (size_t)gr * F + tx * 8) = *(uint4*)hv;
    }
}

// ---------------------------------------------------------------------------
// Gather aggregation (fp16 H): warp per node, lane = 4 features (8B load).
// ---------------------------------------------------------------------------
__device__ __forceinline__ float4 h4_to_f4(uint2 u) {
    float2 fa = __half22float2(*(__half2*)&u.x);
    float2 fb = __half22float2(*(__half2*)&u.y);
    return make_float4(fa.x, fa.y, fb.x, fb.y);
}

template <bool FUSE_HEAD>
__global__ void k_agg(const int* __restrict__ start, const int* __restrict__ srow,
                      const float* __restrict__ dinv, const __half* __restrict__ H,
                      const float* __restrict__ bias,
                      const float* __restrict__ Wl, const float* __restrict__ bl,
                      float* __restrict__ out, int n) {
    int c = blockIdx.x * (blockDim.x >> 5) + (threadIdx.x >> 5);
    int lane = threadIdx.x & 31;
    if (c >= n) return;

    float dc = __ldg(dinv + c);
    int beg = __ldg(start + c);
    int end = __ldg(start + c + 1);

    // self-loop term
    float4 hv = h4_to_f4(__ldg((const uint2*)(H + (size_t)c * F) + lane));
    float d2 = dc * dc;
    float4 acc = make_float4(hv.x * d2, hv.y * d2, hv.z * d2, hv.w * d2);

    int i = beg;
    for (; i + 1 < end; i += 2) {
        int r0 = __ldg(srow + i);
        int r1 = __ldg(srow + i + 1);
        float n0 = __ldg(dinv + r0) * dc;
        float n1 = __ldg(dinv + r1) * dc;
        float4 v0 = h4_to_f4(__ldg((const uint2*)(H + (size_t)r0 * F) + lane));
        float4 v1 = h4_to_f4(__ldg((const uint2*)(H + (size_t)r1 * F) + lane));
        acc.x = fmaf(v0.x, n0, acc.x); acc.y = fmaf(v0.y, n0, acc.y);
        acc.z = fmaf(v0.z, n0, acc.z); acc.w = fmaf(v0.w, n0, acc.w);
        acc.x = fmaf(v1.x, n1, acc.x); acc.y = fmaf(v1.y, n1, acc.y);
        acc.z = fmaf(v1.z, n1, acc.z); acc.w = fmaf(v1.w, n1, acc.w);
    }
    if (i < end) {
        int r0 = __ldg(srow + i);
        float n0 = __ldg(dinv + r0) * dc;
        float4 v0 = h4_to_f4(__ldg((const uint2*)(H + (size_t)r0 * F) + lane));
        acc.x = fmaf(v0.x, n0, acc.x); acc.y = fmaf(v0.y, n0, acc.y);
        acc.z = fmaf(v0.z, n0, acc.z); acc.w = fmaf(v0.w, n0, acc.w);
    }

    float4 bv = __ldg((const float4*)bias + lane);
    acc.x += bv.x; acc.y += bv.y; acc.z += bv.z; acc.w += bv.w;

    if (!FUSE_HEAD) {
        *(float4*)(out + (size_t)c * F + lane * 4) = acc;
    } else {
        float4 w = __ldg((const float4*)Wl + lane);
        float s = fmaxf(acc.x, 0.f) * w.x + fmaxf(acc.y, 0.f) * w.y +
                  fmaxf(acc.z, 0.f) * w.z + fmaxf(acc.w, 0.f) * w.w;
        #pragma unroll
        for (int off = 16; off; off >>= 1) s += __shfl_xor_sync(0xFFFFFFFFu, s, off);
        if (lane == 0) {
            float z = s + __ldg(bl);
            out[c] = 1.0f / (1.0f + expf(-z));
        }
    }
}

// ---------------------------------------------------------------------------
extern "C" void kernel_launch(void* const* d_in, const int* in_sizes, int n_in,
                              void* d_out, int out_size) {
    const float* x  = (const float*)d_in[0];
    const int*   ei = (const int*)  d_in[1];
    const float* W1 = (const float*)d_in[2];
    const float* b1 = (const float*)d_in[3];
    const float* W2 = (const float*)d_in[4];
    const float* b2 = (const float*)d_in[5];
    const float* Wl = (const float*)d_in[6];
    const float* bl = (const float*)d_in[7];

    int n = in_sizes[0] / F;
    int E = in_sizes[1] / 2;
    const int* rowp = ei;
    const int* colp = ei + E;

    int *cnt, *start, *cursor, *bsum, *boff, *srow;
    float *dinv, *a;
    __half* h;
    cudaGetSymbolAddress((void**)&cnt,    g_cnt);
    cudaGetSymbolAddress((void**)&start,  g_start);
    cudaGetSymbolAddress((void**)&cursor, g_cursor);
    cudaGetSymbolAddress((void**)&bsum,   g_bsum);
    cudaGetSymbolAddress((void**)&boff,   g_boff);
    cudaGetSymbolAddress((void**)&srow,   g_srow);
    cudaGetSymbolAddress((void**)&dinv,   g_dinv);
    cudaGetSymbolAddress((void**)&h,      g_h);
    cudaGetSymbolAddress((void**)&a,      g_a);

    const size_t gemm_smem = (size_t)(F * F) * sizeof(float);  // 64KB
    cudaFuncSetAttribute(k_gemm<false>, cudaFuncAttributeMaxDynamicSharedMemorySize, (int)gemm_smem);
    cudaFuncSetAttribute(k_gemm<true>,  cudaFuncAttributeMaxDynamicSharedMemorySize, (int)gemm_smem);

    int nb = (n + SCAN_BLK - 1) / SCAN_BLK;

    // --- degree + counting sort prep ---
    k_zero_cnt<<<(n + 255) / 256, 256>>>(cnt, n);
    k_hist    <<<(E + 255) / 256, 256>>>(colp, cnt, E);
    k_dinv    <<<(n + 255) / 256, 256>>>(cnt, dinv, n);
    k_blocksum<<<nb, 256>>>(cnt, bsum, n);
    k_scanbsum<<<1, 256>>>(bsum, boff, start, nb, n);
    k_writestart<<<nb, 256>>>(cnt, boff, start, cursor, n);
    k_scatter <<<(E + 255) / 256, 256>>>(rowp, colp, cursor, srow, E);

    int gemm_grid = (n + 63) / 64;
    int agg_grid  = (n * 32 + 255) / 256;

    // --- layer 1 ---
    k_gemm<false><<<gemm_grid, 256, gemm_smem>>>(x, W1, h, n);
    k_agg<false> <<<agg_grid, 256>>>(start, srow, dinv, h, b1, nullptr, nullptr, a, n);

    // --- layer 2 + fused head ---
    k_gemm<true><<<gemm_grid, 256, gemm_smem>>>(a, W2, h, n);
    k_agg<true> <<<agg_grid, 256>>>(start, srow, dinv, h, b2, Wl, bl, (float*)d_out, n);
}

// round 4
// speedup vs baseline: 4.0581x; 1.6566x over previous
#include <cuda_runtime.h>
#include <cuda_fp16.h>
#include <cstdint>

#define NMAX 100000
#define EMAX 3200000
#define F 128

// Scratch (device globals — no allocation allowed)
__device__ int    g_cnt   [NMAX];
__device__ int    g_start [NMAX + 1];
__device__ int    g_cursor[NMAX];
__device__ int    g_bsum  [256];
__device__ int    g_boff  [256];
__device__ int    g_srow  [EMAX];             // edge row-ids sorted by col
__device__ float  g_dinv  [NMAX];
__device__ __half g_h     [(size_t)NMAX * F]; // GEMM output (fp16)
__device__ __half g_a     [(size_t)NMAX * F]; // layer-1 agg output (fp16, relu'd)

// ---------------------------------------------------------------------------
// degree histogram / dinv
// ---------------------------------------------------------------------------
__global__ void k_zero_cnt(int* __restrict__ cnt, int n) {
    int i = blockIdx.x * blockDim.x + threadIdx.x;
    if (i < n) cnt[i] = 0;
}

__global__ void k_hist(const int* __restrict__ col, int* __restrict__ cnt, int E) {
    int i = blockIdx.x * blockDim.x + threadIdx.x;
    if (i < E) atomicAdd(&cnt[col[i]], 1);
}

__global__ void k_dinv(const int* __restrict__ cnt, float* __restrict__ dinv, int n) {
    int i = blockIdx.x * blockDim.x + threadIdx.x;
    if (i < n) dinv[i] = rsqrtf((float)(cnt[i] + 1));  // +1 self-loop
}

// ---------------------------------------------------------------------------
// Counting sort of edges by col
// ---------------------------------------------------------------------------
#define SCAN_BLK 1024

__global__ void k_blocksum(const int* __restrict__ cnt, int* __restrict__ bsum, int n) {
    __shared__ int sm[256];
    int t = threadIdx.x, b = blockIdx.x;
    int base = b * SCAN_BLK;
    int s = 0;
    #pragma unroll
    for (int k = 0; k < 4; k++) {
        int i = base + t * 4 + k;
        if (i < n) s += cnt[i];
    }
    sm[t] = s; __syncthreads();
    for (int off = 128; off > 0; off >>= 1) {
        if (t < off) sm[t] += sm[t + off];
        __syncthreads();
    }
    if (t == 0) bsum[b] = sm[0];
}

__global__ void k_scanbsum(const int* __restrict__ bsum, int* __restrict__ boff,
                           int* __restrict__ start, int nb, int n) {
    __shared__ int sm[256];
    int t = threadIdx.x;
    int v = (t < nb) ? bsum[t] : 0;
    sm[t] = v; __syncthreads();
    #pragma unroll
    for (int off = 1; off < 256; off <<= 1) {
        int x = 0;
        if (t >= off) x = sm[t - off];
        __syncthreads();
        sm[t] += x;
        __syncthreads();
    }
    if (t < nb) boff[t] = sm[t] - v;
    if (t == 255) start[n] = sm[255];
}

__global__ void k_writestart(const int* __restrict__ cnt, const int* __restrict__ boff,
                             int* __restrict__ start, int* __restrict__ cursor, int n) {
    __shared__ int sm[256];
    int t = threadIdx.x, b = blockIdx.x;
    int base = b * SCAN_BLK + t * 4;
    int c[4]; int s = 0;
    #pragma unroll
    for (int k = 0; k < 4; k++) {
        c[k] = (base + k < n) ? cnt[base + k] : 0;
        s += c[k];
    }
    sm[t] = s; __syncthreads();
    #pragma unroll
    for (int off = 1; off < 256; off <<= 1) {
        int x = 0;
        if (t >= off) x = sm[t - off];
        __syncthreads();
        sm[t] += x;
        __syncthreads();
    }
    int excl = boff[b] + sm[t] - s;
    #pragma unroll
    for (int k = 0; k < 4; k++) {
        int i = base + k;
        if (i < n) { start[i] = excl; cursor[i] = excl; }
        excl += c[k];
    }
}

__global__ void k_scatter(const int* __restrict__ row, const int* __restrict__ col,
                          int* __restrict__ cursor, int* __restrict__ srow, int E) {
    int i = blockIdx.x * blockDim.x + threadIdx.x;
    if (i >= E) return;
    int c = col[i];
    int pos = atomicAdd(&cursor[c], 1);
    srow[pos] = row[i];
}

// ---------------------------------------------------------------------------
// Tensor-core GEMM: H(fp16) = A @ W,  A [M x 128] (fp32 or fp16), W [128 x 128] fp32.
// CTA = 128x128 tile, full K in smem (fp16, ld=136 -> conflict-free LDSM).
// 8 warps: warp_m = wid&3 (32 rows), warp_n = wid>>2 (64 cols).
// ---------------------------------------------------------------------------
#define SLD 136  // smem leading dim in halfs (272B rows: conflict-free ldmatrix)

__device__ __forceinline__ uint32_t smem_u32(const void* p) {
    return (uint32_t)__cvta_generic_to_shared(p);
}

__device__ __forceinline__ void ldsm_x4(uint32_t* r, uint32_t addr) {
    asm volatile("ldmatrix.sync.aligned.m8n8.x4.shared.b16 {%0,%1,%2,%3}, [%4];"
                 : "=r"(r[0]), "=r"(r[1]), "=r"(r[2]), "=r"(r[3]) : "r"(addr));
}

__device__ __forceinline__ void ldsm_x4_t(uint32_t* r, uint32_t addr) {
    asm volatile("ldmatrix.sync.aligned.m8n8.x4.trans.shared.b16 {%0,%1,%2,%3}, [%4];"
                 : "=r"(r[0]), "=r"(r[1]), "=r"(r[2]), "=r"(r[3]) : "r"(addr));
}

__device__ __forceinline__ void mma16816(float* c, const uint32_t* a,
                                         uint32_t b0, uint32_t b1) {
    asm volatile(
        "mma.sync.aligned.m16n8k16.row.col.f32.f16.f16.f32 "
        "{%0,%1,%2,%3}, {%4,%5,%6,%7}, {%8,%9}, {%0,%1,%2,%3};"
        : "+f"(c[0]), "+f"(c[1]), "+f"(c[2]), "+f"(c[3])
        : "r"(a[0]), "r"(a[1]), "r"(a[2]), "r"(a[3]), "r"(b0), "r"(b1));
}

__device__ __forceinline__ uint2 load_row4(const float* base, int c4) {
    float4 v = __ldg((const float4*)base + c4);
    __half2 h0 = __floats2half2_rn(v.x, v.y);
    __half2 h1 = __floats2half2_rn(v.z, v.w);
    uint2 u;
    u.x = *(uint32_t*)&h0;
    u.y = *(uint32_t*)&h1;
    return u;
}

__device__ __forceinline__ uint2 load_row4(const __half* base, int c4) {
    return __ldg((const uint2*)base + c4);
}

template <typename T>
__global__ void __launch_bounds__(256, 2)
k_gemm_mma(const T* __restrict__ A, const float* __restrict__ W,
           __half* __restrict__ H, int M) {
    extern __shared__ __half smh[];
    __half* As = smh;              // 128 x SLD
    __half* Ws = smh + 128 * SLD;  // 128 x SLD

    const int tid = threadIdx.x;
    const int block_row = blockIdx.x * 128;

    // Load W (fp32 -> fp16) and A tile into smem
    #pragma unroll 4
    for (int i = tid; i < 4096; i += 256) {
        int r = i >> 5, c4 = i & 31;
        *(uint2*)(Ws + r * SLD + c4 * 4) = load_row4(W + r * F, c4);
    }
    #pragma unroll 4
    for (int i = tid; i < 4096; i += 256) {
        int r = i >> 5, c4 = i & 31;
        int gr = block_row + r;
        uint2 u = make_uint2(0u, 0u);
        if (gr < M) u = load_row4(A + (size_t)gr * F, c4);
        *(uint2*)(As + r * SLD + c4 * 4) = u;
    }
    __syncthreads();

    const int wid = tid >> 5, lane = tid & 31;
    const int wm = (wid & 3) * 32;
    const int wn = (wid >> 2) * 64;

    float acc[2][8][4];
    #pragma unroll
    for (int mt = 0; mt < 2; mt++)
        #pragma unroll
        for (int nt = 0; nt < 8; nt++)
            #pragma unroll
            for (int q = 0; q < 4; q++) acc[mt][nt][q] = 0.f;

    const uint32_t As_b = smem_u32(As);
    const uint32_t Ws_b = smem_u32(Ws);
    const int lrow = lane & 15;
    const int lcol = (lane >> 4) * 8;

    #pragma unroll
    for (int kb = 0; kb < 8; kb++) {
        uint32_t a[2][4];
        #pragma unroll
        for (int mt = 0; mt < 2; mt++) {
            int row = wm + mt * 16 + lrow;
            int col = kb * 16 + lcol;
            ldsm_x4(a[mt], As_b + (row * SLD + col) * 2);
        }
        uint32_t b[8][2];
        #pragma unroll
        for (int np = 0; np < 4; np++) {
            int krow = kb * 16 + lrow;
            int ncol = wn + np * 16 + lcol;
            uint32_t r[4];
            ldsm_x4_t(r, Ws_b + (krow * SLD + ncol) * 2);
            b[np * 2][0] = r[0]; b[np * 2][1] = r[1];
            b[np * 2 + 1][0] = r[2]; b[np * 2 + 1][1] = r[3];
        }
        #pragma unroll
        for (int mt = 0; mt < 2; mt++)
            #pragma unroll
            for (int nt = 0; nt < 8; nt++)
                mma16816(acc[mt][nt], a[mt], b[nt][0], b[nt][1]);
    }

    // Epilogue: fp16 store
    #pragma unroll
    for (int mt = 0; mt < 2; mt++) {
        int r0 = block_row + wm + mt * 16 + (lane >> 2);
        int r1 = r0 + 8;
        #pragma unroll
        for (int nt = 0; nt < 8; nt++) {
            int col = wn + nt * 8 + (lane & 3) * 2;
            if (r0 < M)
                *(__half2*)(H + (size_t)r0 * F + col) = __floats2half2_rn(acc[mt][nt][0], acc[mt][nt][1]);
            if (r1 < M)
                *(__half2*)(H + (size_t)r1 * F + col) = __floats2half2_rn(acc[mt][nt][2], acc[mt][nt][3]);
        }
    }
}

// ---------------------------------------------------------------------------
// Gather aggregation (fp16 H): warp per node, lane = 4 features (8B load).
// !FUSE_HEAD: out = fp16 relu(agg + bias)   (feeds next GEMM)
//  FUSE_HEAD: out = sigmoid(dot(relu(agg + bias), Wl) + bl)
// ---------------------------------------------------------------------------
__device__ __forceinline__ float4 h4_to_f4(uint2 u) {
    float2 fa = __half22float2(*(__half2*)&u.x);
    float2 fb = __half22float2(*(__half2*)&u.y);
    return make_float4(fa.x, fa.y, fb.x, fb.y);
}

template <bool FUSE_HEAD>
__global__ void k_agg(const int* __restrict__ start, const int* __restrict__ srow,
                      const float* __restrict__ dinv, const __half* __restrict__ H,
                      const float* __restrict__ bias,
                      const float* __restrict__ Wl, const float* __restrict__ bl,
                      __half* __restrict__ hout, float* __restrict__ fout, int n) {
    int c = blockIdx.x * (blockDim.x >> 5) + (threadIdx.x >> 5);
    int lane = threadIdx.x & 31;
    if (c >= n) return;

    float dc = __ldg(dinv + c);
    int beg = __ldg(start + c);
    int end = __ldg(start + c + 1);

    // self-loop term
    float4 hv = h4_to_f4(__ldg((const uint2*)(H + (size_t)c * F) + lane));
    float d2 = dc * dc;
    float4 acc = make_float4(hv.x * d2, hv.y * d2, hv.z * d2, hv.w * d2);

    int i = beg;
    for (; i + 1 < end; i += 2) {
        int r0 = __ldg(srow + i);
        int r1 = __ldg(srow + i + 1);
        float n0 = __ldg(dinv + r0) * dc;
        float n1 = __ldg(dinv + r1) * dc;
        float4 v0 = h4_to_f4(__ldg((const uint2*)(H + (size_t)r0 * F) + lane));
        float4 v1 = h4_to_f4(__ldg((const uint2*)(H + (size_t)r1 * F) + lane));
        acc.x = fmaf(v0.x, n0, acc.x); acc.y = fmaf(v0.y, n0, acc.y);
        acc.z = fmaf(v0.z, n0, acc.z); acc.w = fmaf(v0.w, n0, acc.w);
        acc.x = fmaf(v1.x, n1, acc.x); acc.y = fmaf(v1.y, n1, acc.y);
        acc.z = fmaf(v1.z, n1, acc.z); acc.w = fmaf(v1.w, n1, acc.w);
    }
    if (i < end) {
        int r0 = __ldg(srow + i);
        float n0 = __ldg(dinv + r0) * dc;
        float4 v0 = h4_to_f4(__ldg((const uint2*)(H + (size_t)r0 * F) + lane));
        acc.x = fmaf(v0.x, n0, acc.x); acc.y = fmaf(v0.y, n0, acc.y);
        acc.z = fmaf(v0.z, n0, acc.z); acc.w = fmaf(v0.w, n0, acc.w);
    }

    float4 bv = __ldg((const float4*)bias + lane);
    acc.x += bv.x; acc.y += bv.y; acc.z += bv.z; acc.w += bv.w;

    if (!FUSE_HEAD) {
        // relu + fp16 for next GEMM
        acc.x = fmaxf(acc.x, 0.f); acc.y = fmaxf(acc.y, 0.f);
        acc.z = fmaxf(acc.z, 0.f); acc.w = fmaxf(acc.w, 0.f);
        __half2 h0 = __floats2half2_rn(acc.x, acc.y);
        __half2 h1 = __floats2half2_rn(acc.z, acc.w);
        uint2 u;
        u.x = *(uint32_t*)&h0;
        u.y = *(uint32_t*)&h1;
        *((uint2*)(hout + (size_t)c * F) + lane) = u;
    } else {
        float4 w = __ldg((const float4*)Wl + lane);
        float s = fmaxf(acc.x, 0.f) * w.x + fmaxf(acc.y, 0.f) * w.y +
                  fmaxf(acc.z, 0.f) * w.z + fmaxf(acc.w, 0.f) * w.w;
        #pragma unroll
        for (int off = 16; off; off >>= 1) s += __shfl_xor_sync(0xFFFFFFFFu, s, off);
        if (lane == 0) {
            float z = s + __ldg(bl);
            fout[c] = 1.0f / (1.0f + expf(-z));
        }
    }
}

// ---------------------------------------------------------------------------
extern "C" void kernel_launch(void* const* d_in, const int* in_sizes, int n_in,
                              void* d_out, int out_size) {
    const float* x  = (const float*)d_in[0];
    const int*   ei = (const int*)  d_in[1];
    const float* W1 = (const float*)d_in[2];
    const float* b1 = (const float*)d_in[3];
    const float* W2 = (const float*)d_in[4];
    const float* b2 = (const float*)d_in[5];
    const float* Wl = (const float*)d_in[6];
    const float* bl = (const float*)d_in[7];

    int n = in_sizes[0] / F;
    int E = in_sizes[1] / 2;
    const int* rowp = ei;
    const int* colp = ei + E;

    int *cnt, *start, *cursor, *bsum, *boff, *srow;
    float *dinv;
    __half *h, *a;
    cudaGetSymbolAddress((void**)&cnt,    g_cnt);
    cudaGetSymbolAddress((void**)&start,  g_start);
    cudaGetSymbolAddress((void**)&cursor, g_cursor);
    cudaGetSymbolAddress((void**)&bsum,   g_bsum);
    cudaGetSymbolAddress((void**)&boff,   g_boff);
    cudaGetSymbolAddress((void**)&srow,   g_srow);
    cudaGetSymbolAddress((void**)&dinv,   g_dinv);
    cudaGetSymbolAddress((void**)&h,      g_h);
    cudaGetSymbolAddress((void**)&a,      g_a);

    const size_t gemm_smem = (size_t)(2 * 128 * SLD) * sizeof(__half);  // 69632B
    cudaFuncSetAttribute(k_gemm_mma<float>,  cudaFuncAttributeMaxDynamicSharedMemorySize, (int)gemm_smem);
    cudaFuncSetAttribute(k_gemm_mma<__half>, cudaFuncAttributeMaxDynamicSharedMemorySize, (int)gemm_smem);

    int nb = (n + SCAN_BLK - 1) / SCAN_BLK;

    // --- degree + counting sort prep ---
    k_zero_cnt<<<(n + 255) / 256, 256>>>(cnt, n);
    k_hist    <<<(E + 255) / 256, 256>>>(colp, cnt, E);
    k_dinv    <<<(n + 255) / 256, 256>>>(cnt, dinv, n);
    k_blocksum<<<nb, 256>>>(cnt, bsum, n);
    k_scanbsum<<<1, 256>>>(bsum, boff, start, nb, n);
    k_writestart<<<nb, 256>>>(cnt, boff, start, cursor, n);
    k_scatter <<<(E + 255) / 256, 256>>>(rowp, colp, cursor, srow, E);

    int gemm_grid = (n + 127) / 128;
    int agg_grid  = (n * 32 + 255) / 256;

    // --- layer 1 ---
    k_gemm_mma<float><<<gemm_grid, 256, gemm_smem>>>(x, W1, h, n);
    k_agg<false>     <<<agg_grid, 256>>>(start, srow, dinv, h, b1, nullptr, nullptr, a, nullptr, n);

    // --- layer 2 + fused head ---
    k_gemm_mma<__half><<<gemm_grid, 256, gemm_smem>>>(a, W2, h, n);
    k_agg<true>       <<<agg_grid, 256>>>(start, srow, dinv, h, b2, Wl, bl, nullptr, (float*)d_out, n);
}

// round 5
// speedup vs baseline: 4.2492x; 1.0471x over previous
#include <cuda_runtime.h>
#include <cstdint>

#define NMAX 100000
#define EMAX 3200000
#define F 128

typedef unsigned short bf16_t;

// Scratch (device globals — no allocation allowed)
__device__ int    g_cnt   [NMAX];
__device__ int    g_start [NMAX + 1];
__device__ int    g_cursor[NMAX];
__device__ int    g_bsum  [256];
__device__ int    g_boff  [256];
__device__ int    g_srow  [EMAX];              // edge row-ids sorted by col
__device__ float  g_dinv  [NMAX];
__device__ bf16_t g_h     [(size_t)NMAX * F];  // GEMM output, prescaled by dinv[row]
__device__ bf16_t g_a     [(size_t)NMAX * F];  // layer-1 agg output (relu'd)

// ---------------------------------------------------------------------------
// bf16 helpers
// ---------------------------------------------------------------------------
__device__ __forceinline__ uint32_t f2_to_bf2(float lo, float hi) {
    uint32_t r;
    asm("cvt.rn.bf16x2.f32 %0, %1, %2;" : "=r"(r) : "f"(hi), "f"(lo));
    return r;
}
__device__ __forceinline__ float bf_lo(uint32_t p) { return __int_as_float(p << 16); }
__device__ __forceinline__ float bf_hi(uint32_t p) { return __int_as_float(p & 0xFFFF0000u); }

// ---------------------------------------------------------------------------
// degree histogram / dinv
// ---------------------------------------------------------------------------
__global__ void k_zero_cnt(int* __restrict__ cnt, int n) {
    int i = blockIdx.x * blockDim.x + threadIdx.x;
    if (i < n) cnt[i] = 0;
}

__global__ void k_hist(const int* __restrict__ col, int* __restrict__ cnt, int E) {
    int i = blockIdx.x * blockDim.x + threadIdx.x;
    if (i < E) atomicAdd(&cnt[col[i]], 1);
}

__global__ void k_dinv(const int* __restrict__ cnt, float* __restrict__ dinv, int n) {
    int i = blockIdx.x * blockDim.x + threadIdx.x;
    if (i < n) dinv[i] = rsqrtf((float)(cnt[i] + 1));  // +1 self-loop
}

// ---------------------------------------------------------------------------
// Counting sort of edges by col
// ---------------------------------------------------------------------------
#define SCAN_BLK 1024

__global__ void k_blocksum(const int* __restrict__ cnt, int* __restrict__ bsum, int n) {
    __shared__ int sm[256];
    int t = threadIdx.x, b = blockIdx.x;
    int base = b * SCAN_BLK;
    int s = 0;
    #pragma unroll
    for (int k = 0; k < 4; k++) {
        int i = base + t * 4 + k;
        if (i < n) s += cnt[i];
    }
    sm[t] = s; __syncthreads();
    for (int off = 128; off > 0; off >>= 1) {
        if (t < off) sm[t] += sm[t + off];
        __syncthreads();
    }
    if (t == 0) bsum[b] = sm[0];
}

__global__ void k_scanbsum(const int* __restrict__ bsum, int* __restrict__ boff,
                           int* __restrict__ start, int nb, int n) {
    __shared__ int sm[256];
    int t = threadIdx.x;
    int v = (t < nb) ? bsum[t] : 0;
    sm[t] = v; __syncthreads();
    #pragma unroll
    for (int off = 1; off < 256; off <<= 1) {
        int x = 0;
        if (t >= off) x = sm[t - off];
        __syncthreads();
        sm[t] += x;
        __syncthreads();
    }
    if (t < nb) boff[t] = sm[t] - v;
    if (t == 255) start[n] = sm[255];
}

__global__ void k_writestart(const int* __restrict__ cnt, const int* __restrict__ boff,
                             int* __restrict__ start, int* __restrict__ cursor, int n) {
    __shared__ int sm[256];
    int t = threadIdx.x, b = blockIdx.x;
    int base = b * SCAN_BLK + t * 4;
    int c[4]; int s = 0;
    #pragma unroll
    for (int k = 0; k < 4; k++) {
        c[k] = (base + k < n) ? cnt[base + k] : 0;
        s += c[k];
    }
    sm[t] = s; __syncthreads();
    #pragma unroll
    for (int off = 1; off < 256; off <<= 1) {
        int x = 0;
        if (t >= off) x = sm[t - off];
        __syncthreads();
        sm[t] += x;
        __syncthreads();
    }
    int excl = boff[b] + sm[t] - s;
    #pragma unroll
    for (int k = 0; k < 4; k++) {
        int i = base + k;
        if (i < n) { start[i] = excl; cursor[i] = excl; }
        excl += c[k];
    }
}

__global__ void k_scatter(const int* __restrict__ row, const int* __restrict__ col,
                          int* __restrict__ cursor, int* __restrict__ srow, int E) {
    int i = blockIdx.x * blockDim.x + threadIdx.x;
    if (i >= E) return;
    int c = col[i];
    int pos = atomicAdd(&cursor[c], 1);
    srow[pos] = row[i];
}

// ---------------------------------------------------------------------------
// Tensor-core GEMM (bf16 mma): H = (A @ W) * dinv[row], stored bf16.
// CTA = 128x128 tile, full K in smem (bf16, ld=136 -> conflict-free LDSM).
// ---------------------------------------------------------------------------
#define SLD 136

__device__ __forceinline__ uint32_t smem_u32(const void* p) {
    return (uint32_t)__cvta_generic_to_shared(p);
}

__device__ __forceinline__ void ldsm_x4(uint32_t* r, uint32_t addr) {
    asm volatile("ldmatrix.sync.aligned.m8n8.x4.shared.b16 {%0,%1,%2,%3}, [%4];"
                 : "=r"(r[0]), "=r"(r[1]), "=r"(r[2]), "=r"(r[3]) : "r"(addr));
}

__device__ __forceinline__ void ldsm_x4_t(uint32_t* r, uint32_t addr) {
    asm volatile("ldmatrix.sync.aligned.m8n8.x4.trans.shared.b16 {%0,%1,%2,%3}, [%4];"
                 : "=r"(r[0]), "=r"(r[1]), "=r"(r[2]), "=r"(r[3]) : "r"(addr));
}

__device__ __forceinline__ void mma_bf16(float* c, const uint32_t* a,
                                         uint32_t b0, uint32_t b1) {
    asm volatile(
        "mma.sync.aligned.m16n8k16.row.col.f32.bf16.bf16.f32 "
        "{%0,%1,%2,%3}, {%4,%5,%6,%7}, {%8,%9}, {%0,%1,%2,%3};"
        : "+f"(c[0]), "+f"(c[1]), "+f"(c[2]), "+f"(c[3])
        : "r"(a[0]), "r"(a[1]), "r"(a[2]), "r"(a[3]), "r"(b0), "r"(b1));
}

__device__ __forceinline__ uint2 load_row4(const float* base, int c4) {
    float4 v = __ldg((const float4*)base + c4);
    uint2 u;
    u.x = f2_to_bf2(v.x, v.y);
    u.y = f2_to_bf2(v.z, v.w);
    return u;
}

__device__ __forceinline__ uint2 load_row4(const bf16_t* base, int c4) {
    return __ldg((const uint2*)base + c4);
}

template <typename T>
__global__ void __launch_bounds__(256, 2)
k_gemm_mma(const T* __restrict__ A, const float* __restrict__ W,
           const float* __restrict__ dinv, bf16_t* __restrict__ H, int M) {
    extern __shared__ bf16_t smh[];
    bf16_t* As = smh;              // 128 x SLD
    bf16_t* Ws = smh + 128 * SLD;  // 128 x SLD

    const int tid = threadIdx.x;
    const int block_row = blockIdx.x * 128;

    #pragma unroll 4
    for (int i = tid; i < 4096; i += 256) {
        int r = i >> 5, c4 = i & 31;
        *(uint2*)(Ws + r * SLD + c4 * 4) = load_row4(W + r * F, c4);
    }
    #pragma unroll 4
    for (int i = tid; i < 4096; i += 256) {
        int r = i >> 5, c4 = i & 31;
        int gr = block_row + r;
        uint2 u = make_uint2(0u, 0u);
        if (gr < M) u = load_row4(A + (size_t)gr * F, c4);
        *(uint2*)(As + r * SLD + c4 * 4) = u;
    }
    __syncthreads();

    const int wid = tid >> 5, lane = tid & 31;
    const int wm = (wid & 3) * 32;
    const int wn = (wid >> 2) * 64;

    float acc[2][8][4];
    #pragma unroll
    for (int mt = 0; mt < 2; mt++)
        #pragma unroll
        for (int nt = 0; nt < 8; nt++)
            #pragma unroll
            for (int q = 0; q < 4; q++) acc[mt][nt][q] = 0.f;

    const uint32_t As_b = smem_u32(As);
    const uint32_t Ws_b = smem_u32(Ws);
    const int lrow = lane & 15;
    const int lcol = (lane >> 4) * 8;

    #pragma unroll
    for (int kb = 0; kb < 8; kb++) {
        uint32_t a[2][4];
        #pragma unroll
        for (int mt = 0; mt < 2; mt++) {
            int row = wm + mt * 16 + lrow;
            int col = kb * 16 + lcol;
            ldsm_x4(a[mt], As_b + (row * SLD + col) * 2);
        }
        uint32_t b[8][2];
        #pragma unroll
        for (int np = 0; np < 4; np++) {
            int krow = kb * 16 + lrow;
            int ncol = wn + np * 16 + lcol;
            uint32_t r[4];
            ldsm_x4_t(r, Ws_b + (krow * SLD + ncol) * 2);
            b[np * 2][0] = r[0]; b[np * 2][1] = r[1];
            b[np * 2 + 1][0] = r[2]; b[np * 2 + 1][1] = r[3];
        }
        #pragma unroll
        for (int mt = 0; mt < 2; mt++)
            #pragma unroll
            for (int nt = 0; nt < 8; nt++)
                mma_bf16(acc[mt][nt], a[mt], b[nt][0], b[nt][1]);
    }

    // Epilogue: scale by dinv[row], store bf16
    #pragma unroll
    for (int mt = 0; mt < 2; mt++) {
        int r0 = block_row + wm + mt * 16 + (lane >> 2);
        int r1 = r0 + 8;
        float d0 = __ldg(dinv + min(r0, M - 1));
        float d1 = __ldg(dinv + min(r1, M - 1));
        #pragma unroll
        for (int nt = 0; nt < 8; nt++) {
            int col = wn + nt * 8 + (lane & 3) * 2;
            if (r0 < M)
                *(uint32_t*)(H + (size_t)r0 * F + col) =
                    f2_to_bf2(acc[mt][nt][0] * d0, acc[mt][nt][1] * d0);
            if (r1 < M)
                *(uint32_t*)(H + (size_t)r1 * F + col) =
                    f2_to_bf2(acc[mt][nt][2] * d1, acc[mt][nt][3] * d1);
        }
    }
}

// ---------------------------------------------------------------------------
// Gather aggregation over prescaled bf16 H':
//   a[c] = dc * ( sum_{r in N(c)} H'[r] + H'[c] ) + bias
// Warp per node group (4 nodes/warp); lane = 4 features (8B load).
// srow read coalesced once per 32 edges, distributed via shuffle.
// ---------------------------------------------------------------------------
#define NPW 4

template <bool FUSE_HEAD>
__global__ void __launch_bounds__(256)
k_agg(const int* __restrict__ start, const int* __restrict__ srow,
      const float* __restrict__ dinv, const bf16_t* __restrict__ H,
      const float* __restrict__ bias,
      const float* __restrict__ Wl, const float* __restrict__ bl,
      bf16_t* __restrict__ hout, float* __restrict__ fout, int n) {
    const int lane = threadIdx.x & 31;
    const int warp = (blockIdx.x * blockDim.x + threadIdx.x) >> 5;
    int c0 = warp * NPW;
    if (c0 >= n) return;
    int c_end = min(c0 + NPW, n);

    float4 bv = __ldg((const float4*)bias + lane);
    float4 wv = make_float4(0.f, 0.f, 0.f, 0.f);
    float blv = 0.f;
    if (FUSE_HEAD) { wv = __ldg((const float4*)Wl + lane); blv = __ldg(bl); }

    for (int c = c0; c < c_end; c++) {
        int beg = __ldg(start + c);
        int end = __ldg(start + c + 1);
        float dc = __ldg(dinv + c);

        // self term (H' already has dinv[c] folded in)
        uint2 su = __ldg((const uint2*)(H + (size_t)c * F) + lane);
        float4 acc = make_float4(bf_lo(su.x), bf_hi(su.x), bf_lo(su.y), bf_hi(su.y));

        for (int i = beg; i < end; i += 32) {
            int idx = i + lane;
            int rr = __ldg(srow + (idx < end ? idx : end - 1));
            int cnt = min(end - i, 32);
            int j = 0;
            for (; j + 1 < cnt; j += 2) {
                int r0 = __shfl_sync(0xFFFFFFFFu, rr, j);
                int r1 = __shfl_sync(0xFFFFFFFFu, rr, j + 1);
                uint2 u0 = __ldg((const uint2*)(H + (size_t)r0 * F) + lane);
                uint2 u1 = __ldg((const uint2*)(H + (size_t)r1 * F) + lane);
                acc.x += bf_lo(u0.x); acc.y += bf_hi(u0.x);
                acc.z += bf_lo(u0.y); acc.w += bf_hi(u0.y);
                acc.x += bf_lo(u1.x); acc.y += bf_hi(u1.x);
                acc.z += bf_lo(u1.y); acc.w += bf_hi(u1.y);
            }
            if (j < cnt) {
                int r0 = __shfl_sync(0xFFFFFFFFu, rr, j);
                uint2 u0 = __ldg((const uint2*)(H + (size_t)r0 * F) + lane);
                acc.x += bf_lo(u0.x); acc.y += bf_hi(u0.x);
                acc.z += bf_lo(u0.y); acc.w += bf_hi(u0.y);
            }
        }

        float4 o = make_float4(fmaf(dc, acc.x, bv.x), fmaf(dc, acc.y, bv.y),
                               fmaf(dc, acc.z, bv.z), fmaf(dc, acc.w, bv.w));

        if (!FUSE_HEAD) {
            o.x = fmaxf(o.x, 0.f); o.y = fmaxf(o.y, 0.f);
            o.z = fmaxf(o.z, 0.f); o.w = fmaxf(o.w, 0.f);
            uint2 u;
            u.x = f2_to_bf2(o.x, o.y);
            u.y = f2_to_bf2(o.z, o.w);
            *((uint2*)(hout + (size_t)c * F) + lane) = u;
        } else {
            float s = fmaxf(o.x, 0.f) * wv.x + fmaxf(o.y, 0.f) * wv.y +
                      fmaxf(o.z, 0.f) * wv.z + fmaxf(o.w, 0.f) * wv.w;
            #pragma unroll
            for (int off = 16; off; off >>= 1) s += __shfl_xor_sync(0xFFFFFFFFu, s, off);
            if (lane == 0) {
                float z = s + blv;
                fout[c] = 1.0f / (1.0f + expf(-z));
            }
        }
    }
}

// ---------------------------------------------------------------------------
extern "C" void kernel_launch(void* const* d_in, const int* in_sizes, int n_in,
                              void* d_out, int out_size) {
    const float* x  = (const float*)d_in[0];
    const int*   ei = (const int*)  d_in[1];
    const float* W1 = (const float*)d_in[2];
    const float* b1 = (const float*)d_in[3];
    const float* W2 = (const float*)d_in[4];
    const float* b2 = (const float*)d_in[5];
    const float* Wl = (const float*)d_in[6];
    const float* bl = (const float*)d_in[7];

    int n = in_sizes[0] / F;
    int E = in_sizes[1] / 2;
    const int* rowp = ei;
    const int* colp = ei + E;

    int *cnt, *start, *cursor, *bsum, *boff, *srow;
    float *dinv;
    bf16_t *h, *a;
    cudaGetSymbolAddress((void**)&cnt,    g_cnt);
    cudaGetSymbolAddress((void**)&start,  g_start);
    cudaGetSymbolAddress((void**)&cursor, g_cursor);
    cudaGetSymbolAddress((void**)&bsum,   g_bsum);
    cudaGetSymbolAddress((void**)&boff,   g_boff);
    cudaGetSymbolAddress((void**)&srow,   g_srow);
    cudaGetSymbolAddress((void**)&dinv,   g_dinv);
    cudaGetSymbolAddress((void**)&h,      g_h);
    cudaGetSymbolAddress((void**)&a,      g_a);

    const size_t gemm_smem = (size_t)(2 * 128 * SLD) * sizeof(bf16_t);
    cudaFuncSetAttribute(k_gemm_mma<float>,  cudaFuncAttributeMaxDynamicSharedMemorySize, (int)gemm_smem);
    cudaFuncSetAttribute(k_gemm_mma<bf16_t>, cudaFuncAttributeMaxDynamicSharedMemorySize, (int)gemm_smem);

    // Side stream + events for overlapping the sort chain with GEMM1.
    // Created once, reused; never destroyed (graph capture forbids destroying
    // a forked stream mid-capture). Falls back to serial if creation fails.
    static cudaStream_t s2 = nullptr;
    static cudaEvent_t evA = nullptr, evB = nullptr;
    static int init_tried = 0;
    if (!init_tried) {
        init_tried = 1;
        if (cudaStreamCreateWithFlags(&s2, cudaStreamNonBlocking) != cudaSuccess) s2 = nullptr;
        if (cudaEventCreateWithFlags(&evA, cudaEventDisableTiming) != cudaSuccess) evA = nullptr;
        if (cudaEventCreateWithFlags(&evB, cudaEventDisableTiming) != cudaSuccess) evB = nullptr;
    }
    bool par = (s2 != nullptr) && (evA != nullptr) && (evB != nullptr);

    int nb = (n + SCAN_BLK - 1) / SCAN_BLK;
    int gemm_grid = (n + 127) / 128;
    int agg_grid  = ((n + NPW - 1) / NPW * 32 + 255) / 256;

    // --- degree + dinv (needed by GEMM1 epilogue) ---
    k_zero_cnt<<<(n + 255) / 256, 256>>>(cnt, n);
    k_hist    <<<(E + 255) / 256, 256>>>(colp, cnt, E);
    k_dinv    <<<(n + 255) / 256, 256>>>(cnt, dinv, n);

    if (par) {
        cudaEventRecord(evA, 0);
        cudaStreamWaitEvent(s2, evA, 0);
        k_blocksum  <<<nb, 256, 0, s2>>>(cnt, bsum, n);
        k_scanbsum  <<<1, 256, 0, s2>>>(bsum, boff, start, nb, n);
        k_writestart<<<nb, 256, 0, s2>>>(cnt, boff, start, cursor, n);
        k_scatter   <<<(E + 255) / 256, 256, 0, s2>>>(rowp, colp, cursor, srow, E);
        cudaEventRecord(evB, s2);
        // GEMM1 on stream 0, overlapped with the sort chain
        k_gemm_mma<float><<<gemm_grid, 256, gemm_smem>>>(x, W1, dinv, h, n);
        cudaStreamWaitEvent(0, evB, 0);
    } else {
        k_blocksum  <<<nb, 256>>>(cnt, bsum, n);
        k_scanbsum  <<<1, 256>>>(bsum, boff, start, nb, n);
        k_writestart<<<nb, 256>>>(cnt, boff, start, cursor, n);
        k_scatter   <<<(E + 255) / 256, 256>>>(rowp, colp, cursor, srow, E);
        k_gemm_mma<float><<<gemm_grid, 256, gemm_smem>>>(x, W1, dinv, h, n);
    }

    // --- layer 1 agg ---
    k_agg<false><<<agg_grid, 256>>>(start, srow, dinv, h, b1, nullptr, nullptr, a, nullptr, n);

    // --- layer 2 + fused head ---
    k_gemm_mma<bf16_t><<<gemm_grid, 256, gemm_smem>>>(a, W2, dinv, h, n);
    k_agg<true><<<agg_grid, 256>>>(start, srow, dinv, h, b2, Wl, bl, nullptr, (float*)d_out, n);
}

// round 7
// speedup vs baseline: 4.4116x; 1.0382x over previous
#include <cuda_runtime.h>
#include <cuda_fp16.h>
#include <cstdint>

#define NMAX 100000
#define EMAX 3200000
#define F 128
#define FP8_SCALE 16.0f

typedef unsigned short bf16_t;

// Scratch (device globals — no allocation allowed)
__device__ int     g_cnt   [NMAX];
__device__ int     g_start [NMAX + 1];
__device__ int     g_cursor[NMAX];
__device__ int     g_bsum  [256];
__device__ int     g_boff  [256];
__device__ int     g_srow  [EMAX];              // edge row-ids sorted by col
__device__ float   g_dinv  [NMAX];
__device__ uint8_t g_h8    [(size_t)NMAX * F];  // layer-1 GEMM out: fp8, prescaled dinv*16
__device__ bf16_t  g_h     [(size_t)NMAX * F];  // layer-2 GEMM out: bf16, prescaled dinv
__device__ bf16_t  g_a     [(size_t)NMAX * F];  // layer-1 agg output (relu'd)

// ---------------------------------------------------------------------------
// numeric helpers
// ---------------------------------------------------------------------------
__device__ __forceinline__ uint32_t f2_to_bf2(float lo, float hi) {
    uint32_t r;
    asm("cvt.rn.bf16x2.f32 %0, %1, %2;" : "=r"(r) : "f"(hi), "f"(lo));
    return r;
}
__device__ __forceinline__ float bf_lo(uint32_t p) { return __int_as_float(p << 16); }
__device__ __forceinline__ float bf_hi(uint32_t p) { return __int_as_float(p & 0xFFFF0000u); }

// two fp32 -> packed e4m3x2 in a .b16 register (byte0 = lo, byte1 = hi)
__device__ __forceinline__ uint16_t f2_to_e4m3x2(float lo, float hi) {
    uint16_t r;
    asm("cvt.rn.satfinite.e4m3x2.f32 %0, %1, %2;" : "=h"(r) : "f"(hi), "f"(lo));
    return r;
}

// 2 packed e4m3 (.b16) -> half2 (exact)
__device__ __forceinline__ __half2 e4m3x2_to_h2(uint16_t v) {
    uint32_t r;
    asm("cvt.rn.f16x2.e4m3x2 %0, %1;" : "=r"(r) : "h"(v));
    return *(__half2*)&r;
}

// 4 packed e4m3 (u32) -> two half2 (p0 = elems 0,1; p1 = elems 2,3)
__device__ __forceinline__ void fp8x4_to_h2(uint32_t u, __half2& p0, __half2& p1) {
    p0 = e4m3x2_to_h2((uint16_t)(u & 0xFFFFu));
    p1 = e4m3x2_to_h2((uint16_t)(u >> 16));
}

// ---------------------------------------------------------------------------
// degree histogram / dinv
// ---------------------------------------------------------------------------
__global__ void k_zero_cnt(int* __restrict__ cnt, int n) {
    int i = blockIdx.x * blockDim.x + threadIdx.x;
    if (i < n) cnt[i] = 0;
}

__global__ void k_hist(const int* __restrict__ col, int* __restrict__ cnt, int E) {
    int i = blockIdx.x * blockDim.x + threadIdx.x;
    if (i < E) atomicAdd(&cnt[col[i]], 1);
}

__global__ void k_dinv(const int* __restrict__ cnt, float* __restrict__ dinv, int n) {
    int i = blockIdx.x * blockDim.x + threadIdx.x;
    if (i < n) dinv[i] = rsqrtf((float)(cnt[i] + 1));  // +1 self-loop
}

// ---------------------------------------------------------------------------
// Counting sort of edges by col
// ---------------------------------------------------------------------------
#define SCAN_BLK 1024

__global__ void k_blocksum(const int* __restrict__ cnt, int* __restrict__ bsum, int n) {
    __shared__ int sm[256];
    int t = threadIdx.x, b = blockIdx.x;
    int base = b * SCAN_BLK;
    int s = 0;
    #pragma unroll
    for (int k = 0; k < 4; k++) {
        int i = base + t * 4 + k;
        if (i < n) s += cnt[i];
    }
    sm[t] = s; __syncthreads();
    for (int off = 128; off > 0; off >>= 1) {
        if (t < off) sm[t] += sm[t + off];
        __syncthreads();
    }
    if (t == 0) bsum[b] = sm[0];
}

__global__ void k_scanbsum(const int* __restrict__ bsum, int* __restrict__ boff,
                           int* __restrict__ start, int nb, int n) {
    __shared__ int sm[256];
    int t = threadIdx.x;
    int v = (t < nb) ? bsum[t] : 0;
    sm[t] = v; __syncthreads();
    #pragma unroll
    for (int off = 1; off < 256; off <<= 1) {
        int x = 0;
        if (t >= off) x = sm[t - off];
        __syncthreads();
        sm[t] += x;
        __syncthreads();
    }
    if (t < nb) boff[t] = sm[t] - v;
    if (t == 255) start[n] = sm[255];
}

__global__ void k_writestart(const int* __restrict__ cnt, const int* __restrict__ boff,
                             int* __restrict__ start, int* __restrict__ cursor, int n) {
    __shared__ int sm[256];
    int t = threadIdx.x, b = blockIdx.x;
    int base = b * SCAN_BLK + t * 4;
    int c[4]; int s = 0;
    #pragma unroll
    for (int k = 0; k < 4; k++) {
        c[k] = (base + k < n) ? cnt[base + k] : 0;
        s += c[k];
    }
    sm[t] = s; __syncthreads();
    #pragma unroll
    for (int off = 1; off < 256; off <<= 1) {
        int x = 0;
        if (t >= off) x = sm[t - off];
        __syncthreads();
        sm[t] += x;
        __syncthreads();
    }
    int excl = boff[b] + sm[t] - s;
    #pragma unroll
    for (int k = 0; k < 4; k++) {
        int i = base + k;
        if (i < n) { start[i] = excl; cursor[i] = excl; }
        excl += c[k];
    }
}

__global__ void k_scatter(const int* __restrict__ row, const int* __restrict__ col,
                          int* __restrict__ cursor, int* __restrict__ srow, int E) {
    int i = blockIdx.x * blockDim.x + threadIdx.x;
    if (i >= E) return;
    int c = col[i];
    int pos = atomicAdd(&cursor[c], 1);
    srow[pos] = row[i];
}

// ---------------------------------------------------------------------------
// Tensor-core GEMM (bf16 mma):
//   FP8OUT=1: H8(fp8) = (A @ W) * dinv[row] * 16
//   FP8OUT=0: H (bf16) = (A @ W) * dinv[row]
// CTA = 128x128 tile, full K in smem (bf16, ld=136 -> conflict-free LDSM).
// ---------------------------------------------------------------------------
#define SLD 136

__device__ __forceinline__ uint32_t smem_u32(const void* p) {
    return (uint32_t)__cvta_generic_to_shared(p);
}

__device__ __forceinline__ void ldsm_x4(uint32_t* r, uint32_t addr) {
    asm volatile("ldmatrix.sync.aligned.m8n8.x4.shared.b16 {%0,%1,%2,%3}, [%4];"
                 : "=r"(r[0]), "=r"(r[1]), "=r"(r[2]), "=r"(r[3]) : "r"(addr));
}

__device__ __forceinline__ void ldsm_x4_t(uint32_t* r, uint32_t addr) {
    asm volatile("ldmatrix.sync.aligned.m8n8.x4.trans.shared.b16 {%0,%1,%2,%3}, [%4];"
                 : "=r"(r[0]), "=r"(r[1]), "=r"(r[2]), "=r"(r[3]) : "r"(addr));
}

__device__ __forceinline__ void mma_bf16(float* c, const uint32_t* a,
                                         uint32_t b0, uint32_t b1) {
    asm volatile(
        "mma.sync.aligned.m16n8k16.row.col.f32.bf16.bf16.f32 "
        "{%0,%1,%2,%3}, {%4,%5,%6,%7}, {%8,%9}, {%0,%1,%2,%3};"
        : "+f"(c[0]), "+f"(c[1]), "+f"(c[2]), "+f"(c[3])
        : "r"(a[0]), "r"(a[1]), "r"(a[2]), "r"(a[3]), "r"(b0), "r"(b1));
}

__device__ __forceinline__ uint2 load_row4(const float* base, int c4) {
    float4 v = __ldg((const float4*)base + c4);
    uint2 u;
    u.x = f2_to_bf2(v.x, v.y);
    u.y = f2_to_bf2(v.z, v.w);
    return u;
}

__device__ __forceinline__ uint2 load_row4(const bf16_t* base, int c4) {
    return __ldg((const uint2*)base + c4);
}

template <typename T, bool FP8OUT>
__global__ void __launch_bounds__(256, 2)
k_gemm_mma(const T* __restrict__ A, const float* __restrict__ W,
           const float* __restrict__ dinv, void* __restrict__ Hout, int M) {
    extern __shared__ bf16_t smh[];
    bf16_t* As = smh;              // 128 x SLD
    bf16_t* Ws = smh + 128 * SLD;  // 128 x SLD

    const int tid = threadIdx.x;
    const int block_row = blockIdx.x * 128;

    #pragma unroll 4
    for (int i = tid; i < 4096; i += 256) {
        int r = i >> 5, c4 = i & 31;
        *(uint2*)(Ws + r * SLD + c4 * 4) = load_row4(W + r * F, c4);
    }
    #pragma unroll 4
    for (int i = tid; i < 4096; i += 256) {
        int r = i >> 5, c4 = i & 31;
        int gr = block_row + r;
        uint2 u = make_uint2(0u, 0u);
        if (gr < M) u = load_row4(A + (size_t)gr * F, c4);
        *(uint2*)(As + r * SLD + c4 * 4) = u;
    }
    __syncthreads();

    const int wid = tid >> 5, lane = tid & 31;
    const int wm = (wid & 3) * 32;
    const int wn = (wid >> 2) * 64;

    float acc[2][8][4];
    #pragma unroll
    for (int mt = 0; mt < 2; mt++)
        #pragma unroll
        for (int nt = 0; nt < 8; nt++)
            #pragma unroll
            for (int q = 0; q < 4; q++) acc[mt][nt][q] = 0.f;

    const uint32_t As_b = smem_u32(As);
    const uint32_t Ws_b = smem_u32(Ws);
    const int lrow = lane & 15;
    const int lcol = (lane >> 4) * 8;

    #pragma unroll
    for (int kb = 0; kb < 8; kb++) {
        uint32_t a[2][4];
        #pragma unroll
        for (int mt = 0; mt < 2; mt++) {
            int row = wm + mt * 16 + lrow;
            int col = kb * 16 + lcol;
            ldsm_x4(a[mt], As_b + (row * SLD + col) * 2);
        }
        uint32_t b[8][2];
        #pragma unroll
        for (int np = 0; np < 4; np++) {
            int krow = kb * 16 + lrow;
            int ncol = wn + np * 16 + lcol;
            uint32_t r[4];
            ldsm_x4_t(r, Ws_b + (krow * SLD + ncol) * 2);
            b[np * 2][0] = r[0]; b[np * 2][1] = r[1];
            b[np * 2 + 1][0] = r[2]; b[np * 2 + 1][1] = r[3];
        }
        #pragma unroll
        for (int mt = 0; mt < 2; mt++)
            #pragma unroll
            for (int nt = 0; nt < 8; nt++)
                mma_bf16(acc[mt][nt], a[mt], b[nt][0], b[nt][1]);
    }

    // Epilogue: scale by dinv[row] (x16 for fp8), store
    #pragma unroll
    for (int mt = 0; mt < 2; mt++) {
        int r0 = block_row + wm + mt * 16 + (lane >> 2);
        int r1 = r0 + 8;
        float d0 = __ldg(dinv + min(r0, M - 1));
        float d1 = __ldg(dinv + min(r1, M - 1));
        if (FP8OUT) { d0 *= FP8_SCALE; d1 *= FP8_SCALE; }
        #pragma unroll
        for (int nt = 0; nt < 8; nt++) {
            int col = wn + nt * 8 + (lane & 3) * 2;
            if (FP8OUT) {
                uint8_t* H8 = (uint8_t*)Hout;
                if (r0 < M)
                    *(uint16_t*)(H8 + (size_t)r0 * F + col) =
                        f2_to_e4m3x2(acc[mt][nt][0] * d0, acc[mt][nt][1] * d0);
                if (r1 < M)
                    *(uint16_t*)(H8 + (size_t)r1 * F + col) =
                        f2_to_e4m3x2(acc[mt][nt][2] * d1, acc[mt][nt][3] * d1);
            } else {
                bf16_t* H = (bf16_t*)Hout;
                if (r0 < M)
                    *(uint32_t*)(H + (size_t)r0 * F + col) =
                        f2_to_bf2(acc[mt][nt][0] * d0, acc[mt][nt][1] * d0);
                if (r1 < M)
                    *(uint32_t*)(H + (size_t)r1 * F + col) =
                        f2_to_bf2(acc[mt][nt][2] * d1, acc[mt][nt][3] * d1);
            }
        }
    }
}

// ---------------------------------------------------------------------------
// Gather aggregation over prescaled H':
//   a[c] = dc_eff * ( sum_{r in N(c)} H'[r] + H'[c] ) + bias
// FP8IN: H' is fp8 (128B rows), lane = 4 features (4B load); batches of 4 edges
//        summed in half2, flushed to fp32 — 1 F2F/edge/lane.
// else:  H' is bf16 (256B rows), lane = 4 features (8B load).
// ---------------------------------------------------------------------------
#define NPW 4

template <bool FUSE_HEAD, bool FP8IN>
__global__ void __launch_bounds__(256)
k_agg(const int* __restrict__ start, const int* __restrict__ srow,
      const float* __restrict__ dinv, const void* __restrict__ Hin,
      const float* __restrict__ bias,
      const float* __restrict__ Wl, const float* __restrict__ bl,
      bf16_t* __restrict__ hout, float* __restrict__ fout, int n) {
    const int lane = threadIdx.x & 31;
    const int warp = (blockIdx.x * blockDim.x + threadIdx.x) >> 5;
    int c0 = warp * NPW;
    if (c0 >= n) return;
    int c_end = min(c0 + NPW, n);

    float4 bv = __ldg((const float4*)bias + lane);
    float4 wv = make_float4(0.f, 0.f, 0.f, 0.f);
    float blv = 0.f;
    if (FUSE_HEAD) { wv = __ldg((const float4*)Wl + lane); blv = __ldg(bl); }

    const uint8_t* H8 = (const uint8_t*)Hin;
    const bf16_t*  Hb = (const bf16_t*)Hin;

    for (int c = c0; c < c_end; c++) {
        int beg = __ldg(start + c);
        int end = __ldg(start + c + 1);
        float dc = __ldg(dinv + c);
        if (FP8IN) dc *= (1.0f / FP8_SCALE);

        float4 acc;
        if (FP8IN) {
            uint32_t su = __ldg((const uint32_t*)(H8 + (size_t)c * F) + lane);
            __half2 pa, pb; fp8x4_to_h2(su, pa, pb);
            float2 fa = __half22float2(pa), fb = __half22float2(pb);
            acc = make_float4(fa.x, fa.y, fb.x, fb.y);
        } else {
            uint2 su = __ldg((const uint2*)(Hb + (size_t)c * F) + lane);
            acc = make_float4(bf_lo(su.x), bf_hi(su.x), bf_lo(su.y), bf_hi(su.y));
        }

        for (int i = beg; i < end; i += 32) {
            int idx = i + lane;
            int rr = __ldg(srow + (idx < end ? idx : end - 1));
            int cnt = min(end - i, 32);
            int j = 0;
            if (FP8IN) {
                for (; j + 4 <= cnt; j += 4) {
                    int r0 = __shfl_sync(0xFFFFFFFFu, rr, j);
                    int r1 = __shfl_sync(0xFFFFFFFFu, rr, j + 1);
                    int r2 = __shfl_sync(0xFFFFFFFFu, rr, j + 2);
                    int r3 = __shfl_sync(0xFFFFFFFFu, rr, j + 3);
                    uint32_t u0 = __ldg((const uint32_t*)(H8 + (size_t)r0 * F) + lane);
                    uint32_t u1 = __ldg((const uint32_t*)(H8 + (size_t)r1 * F) + lane);
                    uint32_t u2 = __ldg((const uint32_t*)(H8 + (size_t)r2 * F) + lane);
                    uint32_t u3 = __ldg((const uint32_t*)(H8 + (size_t)r3 * F) + lane);
                    __half2 a0, b0, a1, b1, a2, b2, a3, b3;
                    fp8x4_to_h2(u0, a0, b0);
                    fp8x4_to_h2(u1, a1, b1);
                    fp8x4_to_h2(u2, a2, b2);
                    fp8x4_to_h2(u3, a3, b3);
                    __half2 sa = __hadd2(__hadd2(a0, a1), __hadd2(a2, a3));
                    __half2 sb = __hadd2(__hadd2(b0, b1), __hadd2(b2, b3));
                    float2 fa = __half22float2(sa), fb = __half22float2(sb);
                    acc.x += fa.x; acc.y += fa.y; acc.z += fb.x; acc.w += fb.y;
                }
                for (; j < cnt; j++) {
                    int r0 = __shfl_sync(0xFFFFFFFFu, rr, j);
                    uint32_t u0 = __ldg((const uint32_t*)(H8 + (size_t)r0 * F) + lane);
                    __half2 pa, pb; fp8x4_to_h2(u0, pa, pb);
                    float2 fa = __half22float2(pa), fb = __half22float2(pb);
                    acc.x += fa.x; acc.y += fa.y; acc.z += fb.x; acc.w += fb.y;
                }
            } else {
                for (; j + 1 < cnt; j += 2) {
                    int r0 = __shfl_sync(0xFFFFFFFFu, rr, j);
                    int r1 = __shfl_sync(0xFFFFFFFFu, rr, j + 1);
                    uint2 u0 = __ldg((const uint2*)(Hb + (size_t)r0 * F) + lane);
                    uint2 u1 = __ldg((const uint2*)(Hb + (size_t)r1 * F) + lane);
                    acc.x += bf_lo(u0.x); acc.y += bf_hi(u0.x);
                    acc.z += bf_lo(u0.y); acc.w += bf_hi(u0.y);
                    acc.x += bf_lo(u1.x); acc.y += bf_hi(u1.x);
                    acc.z += bf_lo(u1.y); acc.w += bf_hi(u1.y);
                }
                if (j < cnt) {
                    int r0 = __shfl_sync(0xFFFFFFFFu, rr, j);
                    uint2 u0 = __ldg((const uint2*)(Hb + (size_t)r0 * F) + lane);
                    acc.x += bf_lo(u0.x); acc.y += bf_hi(u0.x);
                    acc.z += bf_lo(u0.y); acc.w += bf_hi(u0.y);
                }
            }
        }

        float4 o = make_float4(fmaf(dc, acc.x, bv.x), fmaf(dc, acc.y, bv.y),
                               fmaf(dc, acc.z, bv.z), fmaf(dc, acc.w, bv.w));

        if (!FUSE_HEAD) {
            o.x = fmaxf(o.x, 0.f); o.y = fmaxf(o.y, 0.f);
            o.z = fmaxf(o.z, 0.f); o.w = fmaxf(o.w, 0.f);
            uint2 u;
            u.x = f2_to_bf2(o.x, o.y);
            u.y = f2_to_bf2(o.z, o.w);
            *((uint2*)(hout + (size_t)c * F) + lane) = u;
        } else {
            float s = fmaxf(o.x, 0.f) * wv.x + fmaxf(o.y, 0.f) * wv.y +
                      fmaxf(o.z, 0.f) * wv.z + fmaxf(o.w, 0.f) * wv.w;
            #pragma unroll
            for (int off = 16; off; off >>= 1) s += __shfl_xor_sync(0xFFFFFFFFu, s, off);
            if (lane == 0) {
                float z = s + blv;
                fout[c] = 1.0f / (1.0f + expf(-z));
            }
        }
    }
}

// ---------------------------------------------------------------------------
extern "C" void kernel_launch(void* const* d_in, const int* in_sizes, int n_in,
                              void* d_out, int out_size) {
    const float* x  = (const float*)d_in[0];
    const int*   ei = (const int*)  d_in[1];
    const float* W1 = (const float*)d_in[2];
    const float* b1 = (const float*)d_in[3];
    const float* W2 = (const float*)d_in[4];
    const float* b2 = (const float*)d_in[5];
    const float* Wl = (const float*)d_in[6];
    const float* bl = (const float*)d_in[7];

    int n = in_sizes[0] / F;
    int E = in_sizes[1] / 2;
    const int* rowp = ei;
    const int* colp = ei + E;

    int *cnt, *start, *cursor, *bsum, *boff, *srow;
    float *dinv;
    uint8_t *h8;
    bf16_t *h, *a;
    cudaGetSymbolAddress((void**)&cnt,    g_cnt);
    cudaGetSymbolAddress((void**)&start,  g_start);
    cudaGetSymbolAddress((void**)&cursor, g_cursor);
    cudaGetSymbolAddress((void**)&bsum,   g_bsum);
    cudaGetSymbolAddress((void**)&boff,   g_boff);
    cudaGetSymbolAddress((void**)&srow,   g_srow);
    cudaGetSymbolAddress((void**)&dinv,   g_dinv);
    cudaGetSymbolAddress((void**)&h8,     g_h8);
    cudaGetSymbolAddress((void**)&h,      g_h);
    cudaGetSymbolAddress((void**)&a,      g_a);

    const size_t gemm_smem = (size_t)(2 * 128 * SLD) * sizeof(bf16_t);
    cudaFuncSetAttribute((const void*)k_gemm_mma<float, true>,
                         cudaFuncAttributeMaxDynamicSharedMemorySize, (int)gemm_smem);
    cudaFuncSetAttribute((const void*)k_gemm_mma<bf16_t, false>,
                         cudaFuncAttributeMaxDynamicSharedMemorySize, (int)gemm_smem);

    // Side stream + events for overlapping the sort chain with GEMM1.
    static cudaStream_t s2 = nullptr;
    static cudaEvent_t evA = nullptr, evB = nullptr;
    static int init_tried = 0;
    if (!init_tried) {
        init_tried = 1;
        if (cudaStreamCreateWithFlags(&s2, cudaStreamNonBlocking) != cudaSuccess) s2 = nullptr;
        if (cudaEventCreateWithFlags(&evA, cudaEventDisableTiming) != cudaSuccess) evA = nullptr;
        if (cudaEventCreateWithFlags(&evB, cudaEventDisableTiming) != cudaSuccess) evB = nullptr;
    }
    bool par = (s2 != nullptr) && (evA != nullptr) && (evB != nullptr);

    int nb = (n + SCAN_BLK - 1) / SCAN_BLK;
    int gemm_grid = (n + 127) / 128;
    int agg_grid  = ((n + NPW - 1) / NPW * 32 + 255) / 256;

    // --- degree + dinv ---
    k_zero_cnt<<<(n + 255) / 256, 256>>>(cnt, n);
    k_hist    <<<(E + 255) / 256, 256>>>(colp, cnt, E);
    k_dinv    <<<(n + 255) / 256, 256>>>(cnt, dinv, n);

    if (par) {
        cudaEventRecord(evA, 0);
        cudaStreamWaitEvent(s2, evA, 0);
        k_blocksum  <<<nb, 256, 0, s2>>>(cnt, bsum, n);
        k_scanbsum  <<<1, 256, 0, s2>>>(bsum, boff, start, nb, n);
        k_writestart<<<nb, 256, 0, s2>>>(cnt, boff, start, cursor, n);
        k_scatter   <<<(E + 255) / 256, 256, 0, s2>>>(rowp, colp, cursor, srow, E);
        cudaEventRecord(evB, s2);
        k_gemm_mma<float, true><<<gemm_grid, 256, gemm_smem>>>(x, W1, dinv, h8, n);
        cudaStreamWaitEvent(0, evB, 0);
    } else {
        k_blocksum  <<<nb, 256>>>(cnt, bsum, n);
        k_scanbsum  <<<1, 256>>>(bsum, boff, start, nb, n);
        k_writestart<<<nb, 256>>>(cnt, boff, start, cursor, n);
        k_scatter   <<<(E + 255) / 256, 256>>>(rowp, colp, cursor, srow, E);
        k_gemm_mma<float, true><<<gemm_grid, 256, gemm_smem>>>(x, W1, dinv, h8, n);
    }

    // --- layer 1 agg (fp8 gather) ---
    k_agg<false, true><<<agg_grid, 256>>>(start, srow, dinv, h8, b1, nullptr, nullptr, a, nullptr, n);

    // --- layer 2 (bf16) + fused head ---
    k_gemm_mma<bf16_t, false><<<gemm_grid, 256, gemm_smem>>>(a, W2, dinv, h, n);
    k_agg<true, false><<<agg_grid, 256>>>(start, srow, dinv, h, b2, Wl, bl, nullptr, (float*)d_out, n);
}

// round 8
// speedup vs baseline: 4.6948x; 1.0642x over previous
#include <cuda_runtime.h>
#include <cuda_fp16.h>
#include <cstdint>

#define NMAX 100000
#define EMAX 3200000
#define F 128
#define FP8_SCALE 16.0f

typedef unsigned short bf16_t;

// Scratch (device globals — no allocation allowed)
__device__ int     g_cnt   [NMAX];
__device__ int     g_start [NMAX + 1];
__device__ int     g_cursor[NMAX];
__device__ int     g_bsum  [256];
__device__ int     g_boff  [256];
__device__ int     g_srow  [EMAX];              // edge row-ids sorted by col
__device__ float   g_dinv  [NMAX];
__device__ uint8_t g_h8    [(size_t)NMAX * F];  // GEMM out (both layers): fp8, prescaled dinv*16
__device__ bf16_t  g_a     [(size_t)NMAX * F];  // layer-1 agg output (relu'd)

// ---------------------------------------------------------------------------
// numeric helpers
// ---------------------------------------------------------------------------
__device__ __forceinline__ uint32_t f2_to_bf2(float lo, float hi) {
    uint32_t r;
    asm("cvt.rn.bf16x2.f32 %0, %1, %2;" : "=r"(r) : "f"(hi), "f"(lo));
    return r;
}
__device__ __forceinline__ float bf_lo(uint32_t p) { return __int_as_float(p << 16); }
__device__ __forceinline__ float bf_hi(uint32_t p) { return __int_as_float(p & 0xFFFF0000u); }

// two fp32 -> packed e4m3x2 in a .b16 register (byte0 = lo, byte1 = hi)
__device__ __forceinline__ uint16_t f2_to_e4m3x2(float lo, float hi) {
    uint16_t r;
    asm("cvt.rn.satfinite.e4m3x2.f32 %0, %1, %2;" : "=h"(r) : "f"(hi), "f"(lo));
    return r;
}

// 2 packed e4m3 (.b16) -> half2 (exact)
__device__ __forceinline__ __half2 e4m3x2_to_h2(uint16_t v) {
    uint32_t r;
    asm("cvt.rn.f16x2.e4m3x2 %0, %1;" : "=r"(r) : "h"(v));
    return *(__half2*)&r;
}

// 4 packed e4m3 (u32) -> two half2 (p0 = elems 0,1; p1 = elems 2,3)
__device__ __forceinline__ void fp8x4_to_h2(uint32_t u, __half2& p0, __half2& p1) {
    p0 = e4m3x2_to_h2((uint16_t)(u & 0xFFFFu));
    p1 = e4m3x2_to_h2((uint16_t)(u >> 16));
}

// ---------------------------------------------------------------------------
// degree histogram / dinv
// ---------------------------------------------------------------------------
__global__ void k_hist(const int* __restrict__ col, int* __restrict__ cnt, int E) {
    int i = blockIdx.x * blockDim.x + threadIdx.x;
    if (i < E) atomicAdd(&cnt[col[i]], 1);
}

__global__ void k_dinv(const int* __restrict__ cnt, float* __restrict__ dinv, int n) {
    int i = blockIdx.x * blockDim.x + threadIdx.x;
    if (i < n) dinv[i] = rsqrtf((float)(cnt[i] + 1));  // +1 self-loop
}

// ---------------------------------------------------------------------------
// Counting sort of edges by col
// ---------------------------------------------------------------------------
#define SCAN_BLK 1024

__global__ void k_blocksum(const int* __restrict__ cnt, int* __restrict__ bsum, int n) {
    __shared__ int sm[256];
    int t = threadIdx.x, b = blockIdx.x;
    int base = b * SCAN_BLK;
    int s = 0;
    #pragma unroll
    for (int k = 0; k < 4; k++) {
        int i = base + t * 4 + k;
        if (i < n) s += cnt[i];
    }
    sm[t] = s; __syncthreads();
    for (int off = 128; off > 0; off >>= 1) {
        if (t < off) sm[t] += sm[t + off];
        __syncthreads();
    }
    if (t == 0) bsum[b] = sm[0];
}

__global__ void k_scanbsum(const int* __restrict__ bsum, int* __restrict__ boff,
                           int* __restrict__ start, int nb, int n) {
    __shared__ int sm[256];
    int t = threadIdx.x;
    int v = (t < nb) ? bsum[t] : 0;
    sm[t] = v; __syncthreads();
    #pragma unroll
    for (int off = 1; off < 256; off <<= 1) {
        int x = 0;
        if (t >= off) x = sm[t - off];
        __syncthreads();
        sm[t] += x;
        __syncthreads();
    }
    if (t < nb) boff[t] = sm[t] - v;
    if (t == 255) start[n] = sm[255];
}

__global__ void k_writestart(const int* __restrict__ cnt, const int* __restrict__ boff,
                             int* __restrict__ start, int* __restrict__ cursor, int n) {
    __shared__ int sm[256];
    int t = threadIdx.x, b = blockIdx.x;
    int base = b * SCAN_BLK + t * 4;
    int c[4]; int s = 0;
    #pragma unroll
    for (int k = 0; k < 4; k++) {
        c[k] = (base + k < n) ? cnt[base + k] : 0;
        s += c[k];
    }
    sm[t] = s; __syncthreads();
    #pragma unroll
    for (int off = 1; off < 256; off <<= 1) {
        int x = 0;
        if (t >= off) x = sm[t - off];
        __syncthreads();
        sm[t] += x;
        __syncthreads();
    }
    int excl = boff[b] + sm[t] - s;
    #pragma unroll
    for (int k = 0; k < 4; k++) {
        int i = base + k;
        if (i < n) { start[i] = excl; cursor[i] = excl; }
        excl += c[k];
    }
}

__global__ void k_scatter(const int* __restrict__ row, const int* __restrict__ col,
                          int* __restrict__ cursor, int* __restrict__ srow, int E) {
    int i = blockIdx.x * blockDim.x + threadIdx.x;
    if (i >= E) return;
    int c = col[i];
    int pos = atomicAdd(&cursor[c], 1);
    srow[pos] = row[i];
}

// ---------------------------------------------------------------------------
// Tensor-core GEMM (bf16 mma): H8(fp8) = (A @ W) * dinv[row] * 16
// CTA = 128x128 tile, full K in smem (bf16, ld=136 -> conflict-free LDSM).
// ---------------------------------------------------------------------------
#define SLD 136

__device__ __forceinline__ uint32_t smem_u32(const void* p) {
    return (uint32_t)__cvta_generic_to_shared(p);
}

__device__ __forceinline__ void ldsm_x4(uint32_t* r, uint32_t addr) {
    asm volatile("ldmatrix.sync.aligned.m8n8.x4.shared.b16 {%0,%1,%2,%3}, [%4];"
                 : "=r"(r[0]), "=r"(r[1]), "=r"(r[2]), "=r"(r[3]) : "r"(addr));
}

__device__ __forceinline__ void ldsm_x4_t(uint32_t* r, uint32_t addr) {
    asm volatile("ldmatrix.sync.aligned.m8n8.x4.trans.shared.b16 {%0,%1,%2,%3}, [%4];"
                 : "=r"(r[0]), "=r"(r[1]), "=r"(r[2]), "=r"(r[3]) : "r"(addr));
}

__device__ __forceinline__ void mma_bf16(float* c, const uint32_t* a,
                                         uint32_t b0, uint32_t b1) {
    asm volatile(
        "mma.sync.aligned.m16n8k16.row.col.f32.bf16.bf16.f32 "
        "{%0,%1,%2,%3}, {%4,%5,%6,%7}, {%8,%9}, {%0,%1,%2,%3};"
        : "+f"(c[0]), "+f"(c[1]), "+f"(c[2]), "+f"(c[3])
        : "r"(a[0]), "r"(a[1]), "r"(a[2]), "r"(a[3]), "r"(b0), "r"(b1));
}

__device__ __forceinline__ uint2 load_row4(const float* base, int c4) {
    float4 v = __ldg((const float4*)base + c4);
    uint2 u;
    u.x = f2_to_bf2(v.x, v.y);
    u.y = f2_to_bf2(v.z, v.w);
    return u;
}

__device__ __forceinline__ uint2 load_row4(const bf16_t* base, int c4) {
    return __ldg((const uint2*)base + c4);
}

template <typename T>
__global__ void __launch_bounds__(256, 2)
k_gemm_mma(const T* __restrict__ A, const float* __restrict__ W,
           const float* __restrict__ dinv, uint8_t* __restrict__ H8, int M) {
    extern __shared__ bf16_t smh[];
    bf16_t* As = smh;              // 128 x SLD
    bf16_t* Ws = smh + 128 * SLD;  // 128 x SLD

    const int tid = threadIdx.x;
    const int block_row = blockIdx.x * 128;

    #pragma unroll 4
    for (int i = tid; i < 4096; i += 256) {
        int r = i >> 5, c4 = i & 31;
        *(uint2*)(Ws + r * SLD + c4 * 4) = load_row4(W + r * F, c4);
    }
    #pragma unroll 4
    for (int i = tid; i < 4096; i += 256) {
        int r = i >> 5, c4 = i & 31;
        int gr = block_row + r;
        uint2 u = make_uint2(0u, 0u);
        if (gr < M) u = load_row4(A + (size_t)gr * F, c4);
        *(uint2*)(As + r * SLD + c4 * 4) = u;
    }
    __syncthreads();

    const int wid = tid >> 5, lane = tid & 31;
    const int wm = (wid & 3) * 32;
    const int wn = (wid >> 2) * 64;

    float acc[2][8][4];
    #pragma unroll
    for (int mt = 0; mt < 2; mt++)
        #pragma unroll
        for (int nt = 0; nt < 8; nt++)
            #pragma unroll
            for (int q = 0; q < 4; q++) acc[mt][nt][q] = 0.f;

    const uint32_t As_b = smem_u32(As);
    const uint32_t Ws_b = smem_u32(Ws);
    const int lrow = lane & 15;
    const int lcol = (lane >> 4) * 8;

    #pragma unroll
    for (int kb = 0; kb < 8; kb++) {
        uint32_t a[2][4];
        #pragma unroll
        for (int mt = 0; mt < 2; mt++) {
            int row = wm + mt * 16 + lrow;
            int col = kb * 16 + lcol;
            ldsm_x4(a[mt], As_b + (row * SLD + col) * 2);
        }
        uint32_t b[8][2];
        #pragma unroll
        for (int np = 0; np < 4; np++) {
            int krow = kb * 16 + lrow;
            int ncol = wn + np * 16 + lcol;
            uint32_t r[4];
            ldsm_x4_t(r, Ws_b + (krow * SLD + ncol) * 2);
            b[np * 2][0] = r[0]; b[np * 2][1] = r[1];
            b[np * 2 + 1][0] = r[2]; b[np * 2 + 1][1] = r[3];
        }
        #pragma unroll
        for (int mt = 0; mt < 2; mt++)
            #pragma unroll
            for (int nt = 0; nt < 8; nt++)
                mma_bf16(acc[mt][nt], a[mt], b[nt][0], b[nt][1]);
    }

    // Epilogue: scale by dinv[row]*16, store fp8
    #pragma unroll
    for (int mt = 0; mt < 2; mt++) {
        int r0 = block_row + wm + mt * 16 + (lane >> 2);
        int r1 = r0 + 8;
        float d0 = __ldg(dinv + min(r0, M - 1)) * FP8_SCALE;
        float d1 = __ldg(dinv + min(r1, M - 1)) * FP8_SCALE;
        #pragma unroll
        for (int nt = 0; nt < 8; nt++) {
            int col = wn + nt * 8 + (lane & 3) * 2;
            if (r0 < M)
                *(uint16_t*)(H8 + (size_t)r0 * F + col) =
                    f2_to_e4m3x2(acc[mt][nt][0] * d0, acc[mt][nt][1] * d0);
            if (r1 < M)
                *(uint16_t*)(H8 + (size_t)r1 * F + col) =
                    f2_to_e4m3x2(acc[mt][nt][2] * d1, acc[mt][nt][3] * d1);
        }
    }
}

// ---------------------------------------------------------------------------
// Gather aggregation over prescaled fp8 H' (128B rows):
//   a[c] = (dc/16) * ( sum_{r in N(c)} H'[r] + H'[c] ) + bias
// Warp handles 4 nodes; lane = 4 features (4B load); 4 edges batched in half2.
// ---------------------------------------------------------------------------
#define NPW 4

template <bool FUSE_HEAD>
__global__ void __launch_bounds__(256)
k_agg(const int* __restrict__ start, const int* __restrict__ srow,
      const float* __restrict__ dinv, const uint8_t* __restrict__ H8,
      const float* __restrict__ bias,
      const float* __restrict__ Wl, const float* __restrict__ bl,
      bf16_t* __restrict__ hout, float* __restrict__ fout, int n) {
    const int lane = threadIdx.x & 31;
    const int warp = (blockIdx.x * blockDim.x + threadIdx.x) >> 5;
    int c0 = warp * NPW;
    if (c0 >= n) return;
    int c_end = min(c0 + NPW, n);

    float4 bv = __ldg((const float4*)bias + lane);
    float4 wv = make_float4(0.f, 0.f, 0.f, 0.f);
    float blv = 0.f;
    if (FUSE_HEAD) { wv = __ldg((const float4*)Wl + lane); blv = __ldg(bl); }

    for (int c = c0; c < c_end; c++) {
        int beg = __ldg(start + c);
        int end = __ldg(start + c + 1);
        float dc = __ldg(dinv + c) * (1.0f / FP8_SCALE);

        uint32_t su = __ldg((const uint32_t*)(H8 + (size_t)c * F) + lane);
        __half2 spa, spb; fp8x4_to_h2(su, spa, spb);
        float2 sfa = __half22float2(spa), sfb = __half22float2(spb);
        float4 acc = make_float4(sfa.x, sfa.y, sfb.x, sfb.y);

        for (int i = beg; i < end; i += 32) {
            int idx = i + lane;
            int rr = __ldg(srow + (idx < end ? idx : end - 1));
            int cnt = min(end - i, 32);
            int j = 0;
            for (; j + 4 <= cnt; j += 4) {
                int r0 = __shfl_sync(0xFFFFFFFFu, rr, j);
                int r1 = __shfl_sync(0xFFFFFFFFu, rr, j + 1);
                int r2 = __shfl_sync(0xFFFFFFFFu, rr, j + 2);
                int r3 = __shfl_sync(0xFFFFFFFFu, rr, j + 3);
                uint32_t u0 = __ldg((const uint32_t*)(H8 + (size_t)r0 * F) + lane);
                uint32_t u1 = __ldg((const uint32_t*)(H8 + (size_t)r1 * F) + lane);
                uint32_t u2 = __ldg((const uint32_t*)(H8 + (size_t)r2 * F) + lane);
                uint32_t u3 = __ldg((const uint32_t*)(H8 + (size_t)r3 * F) + lane);
                __half2 a0, b0, a1, b1, a2, b2, a3, b3;
                fp8x4_to_h2(u0, a0, b0);
                fp8x4_to_h2(u1, a1, b1);
                fp8x4_to_h2(u2, a2, b2);
                fp8x4_to_h2(u3, a3, b3);
                __half2 sa = __hadd2(__hadd2(a0, a1), __hadd2(a2, a3));
                __half2 sb = __hadd2(__hadd2(b0, b1), __hadd2(b2, b3));
                float2 fa = __half22float2(sa), fb = __half22float2(sb);
                acc.x += fa.x; acc.y += fa.y; acc.z += fb.x; acc.w += fb.y;
            }
            for (; j < cnt; j++) {
                int r0 = __shfl_sync(0xFFFFFFFFu, rr, j);
                uint32_t u0 = __ldg((const uint32_t*)(H8 + (size_t)r0 * F) + lane);
                __half2 pa, pb; fp8x4_to_h2(u0, pa, pb);
                float2 fa = __half22float2(pa), fb = __half22float2(pb);
                acc.x += fa.x; acc.y += fa.y; acc.z += fb.x; acc.w += fb.y;
            }
        }

        float4 o = make_float4(fmaf(dc, acc.x, bv.x), fmaf(dc, acc.y, bv.y),
                               fmaf(dc, acc.z, bv.z), fmaf(dc, acc.w, bv.w));

        if (!FUSE_HEAD) {
            o.x = fmaxf(o.x, 0.f); o.y = fmaxf(o.y, 0.f);
            o.z = fmaxf(o.z, 0.f); o.w = fmaxf(o.w, 0.f);
            uint2 u;
            u.x = f2_to_bf2(o.x, o.y);
            u.y = f2_to_bf2(o.z, o.w);
            *((uint2*)(hout + (size_t)c * F) + lane) = u;
        } else {
            float s = fmaxf(o.x, 0.f) * wv.x + fmaxf(o.y, 0.f) * wv.y +
                      fmaxf(o.z, 0.f) * wv.z + fmaxf(o.w, 0.f) * wv.w;
            #pragma unroll
            for (int off = 16; off; off >>= 1) s += __shfl_xor_sync(0xFFFFFFFFu, s, off);
            if (lane == 0) {
                float z = s + blv;
                fout[c] = 1.0f / (1.0f + expf(-z));
            }
        }
    }
}

// ---------------------------------------------------------------------------
extern "C" void kernel_launch(void* const* d_in, const int* in_sizes, int n_in,
                              void* d_out, int out_size) {
    const float* x  = (const float*)d_in[0];
    const int*   ei = (const int*)  d_in[1];
    const float* W1 = (const float*)d_in[2];
    const float* b1 = (const float*)d_in[3];
    const float* W2 = (const float*)d_in[4];
    const float* b2 = (const float*)d_in[5];
    const float* Wl = (const float*)d_in[6];
    const float* bl = (const float*)d_in[7];

    int n = in_sizes[0] / F;
    int E = in_sizes[1] / 2;
    const int* rowp = ei;
    const int* colp = ei + E;

    int *cnt, *start, *cursor, *bsum, *boff, *srow;
    float *dinv;
    uint8_t *h8;
    bf16_t *a;
    cudaGetSymbolAddress((void**)&cnt,    g_cnt);
    cudaGetSymbolAddress((void**)&start,  g_start);
    cudaGetSymbolAddress((void**)&cursor, g_cursor);
    cudaGetSymbolAddress((void**)&bsum,   g_bsum);
    cudaGetSymbolAddress((void**)&boff,   g_boff);
    cudaGetSymbolAddress((void**)&srow,   g_srow);
    cudaGetSymbolAddress((void**)&dinv,   g_dinv);
    cudaGetSymbolAddress((void**)&h8,     g_h8);
    cudaGetSymbolAddress((void**)&a,      g_a);

    const size_t gemm_smem = (size_t)(2 * 128 * SLD) * sizeof(bf16_t);
    cudaFuncSetAttribute((const void*)k_gemm_mma<float>,
                         cudaFuncAttributeMaxDynamicSharedMemorySize, (int)gemm_smem);
    cudaFuncSetAttribute((const void*)k_gemm_mma<bf16_t>,
                         cudaFuncAttributeMaxDynamicSharedMemorySize, (int)gemm_smem);

    // Side stream + events for overlapping the sort chain with GEMM1.
    static cudaStream_t s2 = nullptr;
    static cudaEvent_t evA = nullptr, evB = nullptr;
    static int init_tried = 0;
    if (!init_tried) {
        init_tried = 1;
        if (cudaStreamCreateWithFlags(&s2, cudaStreamNonBlocking) != cudaSuccess) s2 = nullptr;
        if (cudaEventCreateWithFlags(&evA, cudaEventDisableTiming) != cudaSuccess) evA = nullptr;
        if (cudaEventCreateWithFlags(&evB, cudaEventDisableTiming) != cudaSuccess) evB = nullptr;
    }
    bool par = (s2 != nullptr) && (evA != nullptr) && (evB != nullptr);

    int nb = (n + SCAN_BLK - 1) / SCAN_BLK;
    int gemm_grid = (n + 127) / 128;
    int agg_grid  = ((n + NPW - 1) / NPW * 32 + 255) / 256;

    // --- degree + dinv (cnt zeroed via memset node, not a kernel launch) ---
    cudaMemsetAsync(cnt, 0, (size_t)n * sizeof(int), 0);
    k_hist<<<(E + 255) / 256, 256>>>(colp, cnt, E);       // launch 1
    k_dinv<<<(n + 255) / 256, 256>>>(cnt, dinv, n);       // launch 2

    if (par) {
        cudaEventRecord(evA, 0);
        cudaStreamWaitEvent(s2, evA, 0);
        k_blocksum<<<nb, 256, 0, s2>>>(cnt, bsum, n);                       // launch 3
        k_gemm_mma<float><<<gemm_grid, 256, gemm_smem>>>(x, W1, dinv, h8, n); // launch 4 (profiled)
        k_scanbsum  <<<1, 256, 0, s2>>>(bsum, boff, start, nb, n);          // launch 5
        k_writestart<<<nb, 256, 0, s2>>>(cnt, boff, start, cursor, n);      // launch 6
        k_scatter   <<<(E + 255) / 256, 256, 0, s2>>>(rowp, colp, cursor, srow, E); // launch 7
        cudaEventRecord(evB, s2);
        cudaStreamWaitEvent(0, evB, 0);
    } else {
        k_blocksum  <<<nb, 256>>>(cnt, bsum, n);
        k_gemm_mma<float><<<gemm_grid, 256, gemm_smem>>>(x, W1, dinv, h8, n);
        k_scanbsum  <<<1, 256>>>(bsum, boff, start, nb, n);
        k_writestart<<<nb, 256>>>(cnt, boff, start, cursor, n);
        k_scatter   <<<(E + 255) / 256, 256>>>(rowp, colp, cursor, srow, E);
    }

    // --- layer 1 agg (fp8 gather) -> bf16 a ---
    k_agg<false><<<agg_grid, 256>>>(start, srow, dinv, h8, b1, nullptr, nullptr, a, nullptr, n);

    // --- layer 2 (fp8 out) + fused head (fp8 gather) ---
    k_gemm_mma<bf16_t><<<gemm_grid, 256, gemm_smem>>>(a, W2, dinv, h8, n);
    k_agg<true><<<agg_grid, 256>>>(start, srow, dinv, h8, b2, Wl, bl, nullptr, (float*)d_out, n);
}

// round 9
// speedup vs baseline: 4.8261x; 1.0280x over previous
#include <cuda_runtime.h>
#include <cuda_fp16.h>
#include <cstdint>

#define NMAX 100000
#define EMAX 3200000
#define F 128
#define FP8_SCALE 16.0f

typedef unsigned short bf16_t;

// Scratch (device globals — no allocation allowed)
__device__ int     g_cnt   [NMAX];
__device__ int     g_start [NMAX + 1];
__device__ int     g_cursor[NMAX];
__device__ int     g_bsum  [256];
__device__ int     g_boff  [256];
__device__ int     g_srow  [EMAX];              // edge row-ids sorted by col
__device__ float   g_dinv  [NMAX];
__device__ uint8_t g_h8    [(size_t)NMAX * F];  // GEMM out (both layers): fp8, prescaled dinv*16
__device__ uint8_t g_a8    [(size_t)NMAX * F];  // layer-1 agg output: fp8, relu'd, *16

// ---------------------------------------------------------------------------
// numeric helpers
// ---------------------------------------------------------------------------
__device__ __forceinline__ uint32_t f2_to_bf2(float lo, float hi) {
    uint32_t r;
    asm("cvt.rn.bf16x2.f32 %0, %1, %2;" : "=r"(r) : "f"(hi), "f"(lo));
    return r;
}

__device__ __forceinline__ uint16_t f2_to_e4m3x2(float lo, float hi) {
    uint16_t r;
    asm("cvt.rn.satfinite.e4m3x2.f32 %0, %1, %2;" : "=h"(r) : "f"(hi), "f"(lo));
    return r;
}

__device__ __forceinline__ __half2 e4m3x2_to_h2(uint16_t v) {
    uint32_t r;
    asm("cvt.rn.f16x2.e4m3x2 %0, %1;" : "=r"(r) : "h"(v));
    return *(__half2*)&r;
}

__device__ __forceinline__ void fp8x4_to_h2(uint32_t u, __half2& p0, __half2& p1) {
    p0 = e4m3x2_to_h2((uint16_t)(u & 0xFFFFu));
    p1 = e4m3x2_to_h2((uint16_t)(u >> 16));
}

// ---------------------------------------------------------------------------
// degree histogram / dinv
// ---------------------------------------------------------------------------
__global__ void k_hist(const int* __restrict__ col, int* __restrict__ cnt, int E) {
    int i = blockIdx.x * blockDim.x + threadIdx.x;
    if (i < E) atomicAdd(&cnt[col[i]], 1);
}

__global__ void k_dinv(const int* __restrict__ cnt, float* __restrict__ dinv, int n) {
    int i = blockIdx.x * blockDim.x + threadIdx.x;
    if (i < n) dinv[i] = rsqrtf((float)(cnt[i] + 1));  // +1 self-loop
}

// ---------------------------------------------------------------------------
// Counting sort of edges by col
// ---------------------------------------------------------------------------
#define SCAN_BLK 1024

__global__ void k_blocksum(const int* __restrict__ cnt, int* __restrict__ bsum, int n) {
    __shared__ int sm[256];
    int t = threadIdx.x, b = blockIdx.x;
    int base = b * SCAN_BLK;
    int s = 0;
    #pragma unroll
    for (int k = 0; k < 4; k++) {
        int i = base + t * 4 + k;
        if (i < n) s += cnt[i];
    }
    sm[t] = s; __syncthreads();
    for (int off = 128; off > 0; off >>= 1) {
        if (t < off) sm[t] += sm[t + off];
        __syncthreads();
    }
    if (t == 0) bsum[b] = sm[0];
}

__global__ void k_scanbsum(const int* __restrict__ bsum, int* __restrict__ boff,
                           int* __restrict__ start, int nb, int n) {
    __shared__ int sm[256];
    int t = threadIdx.x;
    int v = (t < nb) ? bsum[t] : 0;
    sm[t] = v; __syncthreads();
    #pragma unroll
    for (int off = 1; off < 256; off <<= 1) {
        int x = 0;
        if (t >= off) x = sm[t - off];
        __syncthreads();
        sm[t] += x;
        __syncthreads();
    }
    if (t < nb) boff[t] = sm[t] - v;
    if (t == 255) start[n] = sm[255];
}

__global__ void k_writestart(const int* __restrict__ cnt, const int* __restrict__ boff,
                             int* __restrict__ start, int* __restrict__ cursor, int n) {
    __shared__ int sm[256];
    int t = threadIdx.x, b = blockIdx.x;
    int base = b * SCAN_BLK + t * 4;
    int c[4]; int s = 0;
    #pragma unroll
    for (int k = 0; k < 4; k++) {
        c[k] = (base + k < n) ? cnt[base + k] : 0;
        s += c[k];
    }
    sm[t] = s; __syncthreads();
    #pragma unroll
    for (int off = 1; off < 256; off <<= 1) {
        int x = 0;
        if (t >= off) x = sm[t - off];
        __syncthreads();
        sm[t] += x;
        __syncthreads();
    }
    int excl = boff[b] + sm[t] - s;
    #pragma unroll
    for (int k = 0; k < 4; k++) {
        int i = base + k;
        if (i < n) { start[i] = excl; cursor[i] = excl; }
        excl += c[k];
    }
}

__global__ void k_scatter(const int* __restrict__ row, const int* __restrict__ col,
                          int* __restrict__ cursor, int* __restrict__ srow, int E) {
    int i = blockIdx.x * blockDim.x + threadIdx.x;
    if (i >= E) return;
    int c = col[i];
    int pos = atomicAdd(&cursor[c], 1);
    srow[pos] = row[i];
}

// ---------------------------------------------------------------------------
// Tensor-core GEMM (bf16 mma): H8(fp8) = (A @ W) * dinv[row] * esc
// A may be fp32 (layer 1) or fp8 (layer 2; values carry x16 already, esc=1).
// CTA = 128x128 tile, full K in smem (bf16, ld=136 -> conflict-free LDSM).
// ---------------------------------------------------------------------------
#define SLD 136

__device__ __forceinline__ uint32_t smem_u32(const void* p) {
    return (uint32_t)__cvta_generic_to_shared(p);
}

__device__ __forceinline__ void ldsm_x4(uint32_t* r, uint32_t addr) {
    asm volatile("ldmatrix.sync.aligned.m8n8.x4.shared.b16 {%0,%1,%2,%3}, [%4];"
                 : "=r"(r[0]), "=r"(r[1]), "=r"(r[2]), "=r"(r[3]) : "r"(addr));
}

__device__ __forceinline__ void ldsm_x4_t(uint32_t* r, uint32_t addr) {
    asm volatile("ldmatrix.sync.aligned.m8n8.x4.trans.shared.b16 {%0,%1,%2,%3}, [%4];"
                 : "=r"(r[0]), "=r"(r[1]), "=r"(r[2]), "=r"(r[3]) : "r"(addr));
}

__device__ __forceinline__ void mma_bf16(float* c, const uint32_t* a,
                                         uint32_t b0, uint32_t b1) {
    asm volatile(
        "mma.sync.aligned.m16n8k16.row.col.f32.bf16.bf16.f32 "
        "{%0,%1,%2,%3}, {%4,%5,%6,%7}, {%8,%9}, {%0,%1,%2,%3};"
        : "+f"(c[0]), "+f"(c[1]), "+f"(c[2]), "+f"(c[3])
        : "r"(a[0]), "r"(a[1]), "r"(a[2]), "r"(a[3]), "r"(b0), "r"(b1));
}

__device__ __forceinline__ uint2 load_row4(const float* base, int c4) {
    float4 v = __ldg((const float4*)base + c4);
    uint2 u;
    u.x = f2_to_bf2(v.x, v.y);
    u.y = f2_to_bf2(v.z, v.w);
    return u;
}

// fp8 row load: 4 e4m3 -> bf16x2 pair (exact: e4m3 mantissa fits bf16)
__device__ __forceinline__ uint2 load_row4(const uint8_t* base, int c4) {
    uint32_t u = __ldg((const uint32_t*)base + c4);
    __half2 p0, p1; fp8x4_to_h2(u, p0, p1);
    float2 f0 = __half22float2(p0), f1 = __half22float2(p1);
    uint2 r;
    r.x = f2_to_bf2(f0.x, f0.y);
    r.y = f2_to_bf2(f1.x, f1.y);
    return r;
}

template <typename T>
__global__ void __launch_bounds__(256, 2)
k_gemm_mma(const T* __restrict__ A, const float* __restrict__ W,
           const float* __restrict__ dinv, uint8_t* __restrict__ H8,
           float esc, int M) {
    extern __shared__ bf16_t smh[];
    bf16_t* As = smh;              // 128 x SLD
    bf16_t* Ws = smh + 128 * SLD;  // 128 x SLD

    const int tid = threadIdx.x;
    const int block_row = blockIdx.x * 128;

    #pragma unroll 4
    for (int i = tid; i < 4096; i += 256) {
        int r = i >> 5, c4 = i & 31;
        *(uint2*)(Ws + r * SLD + c4 * 4) = load_row4(W + r * F, c4);
    }
    #pragma unroll 4
    for (int i = tid; i < 4096; i += 256) {
        int r = i >> 5, c4 = i & 31;
        int gr = block_row + r;
        uint2 u = make_uint2(0u, 0u);
        if (gr < M) u = load_row4(A + (size_t)gr * F, c4);
        *(uint2*)(As + r * SLD + c4 * 4) = u;
    }
    __syncthreads();

    const int wid = tid >> 5, lane = tid & 31;
    const int wm = (wid & 3) * 32;
    const int wn = (wid >> 2) * 64;

    float acc[2][8][4];
    #pragma unroll
    for (int mt = 0; mt < 2; mt++)
        #pragma unroll
        for (int nt = 0; nt < 8; nt++)
            #pragma unroll
            for (int q = 0; q < 4; q++) acc[mt][nt][q] = 0.f;

    const uint32_t As_b = smem_u32(As);
    const uint32_t Ws_b = smem_u32(Ws);
    const int lrow = lane & 15;
    const int lcol = (lane >> 4) * 8;

    #pragma unroll
    for (int kb = 0; kb < 8; kb++) {
        uint32_t a[2][4];
        #pragma unroll
        for (int mt = 0; mt < 2; mt++) {
            int row = wm + mt * 16 + lrow;
            int col = kb * 16 + lcol;
            ldsm_x4(a[mt], As_b + (row * SLD + col) * 2);
        }
        uint32_t b[8][2];
        #pragma unroll
        for (int np = 0; np < 4; np++) {
            int krow = kb * 16 + lrow;
            int ncol = wn + np * 16 + lcol;
            uint32_t r[4];
            ldsm_x4_t(r, Ws_b + (krow * SLD + ncol) * 2);
            b[np * 2][0] = r[0]; b[np * 2][1] = r[1];
            b[np * 2 + 1][0] = r[2]; b[np * 2 + 1][1] = r[3];
        }
        #pragma unroll
        for (int mt = 0; mt < 2; mt++)
            #pragma unroll
            for (int nt = 0; nt < 8; nt++)
                mma_bf16(acc[mt][nt], a[mt], b[nt][0], b[nt][1]);
    }

    // Epilogue: scale by dinv[row]*esc, store fp8
    #pragma unroll
    for (int mt = 0; mt < 2; mt++) {
        int r0 = block_row + wm + mt * 16 + (lane >> 2);
        int r1 = r0 + 8;
        float d0 = __ldg(dinv + min(r0, M - 1)) * esc;
        float d1 = __ldg(dinv + min(r1, M - 1)) * esc;
        #pragma unroll
        for (int nt = 0; nt < 8; nt++) {
            int col = wn + nt * 8 + (lane & 3) * 2;
            if (r0 < M)
                *(uint16_t*)(H8 + (size_t)r0 * F + col) =
                    f2_to_e4m3x2(acc[mt][nt][0] * d0, acc[mt][nt][1] * d0);
            if (r1 < M)
                *(uint16_t*)(H8 + (size_t)r1 * F + col) =
                    f2_to_e4m3x2(acc[mt][nt][2] * d1, acc[mt][nt][3] * d1);
        }
    }
}

// ---------------------------------------------------------------------------
// Gather aggregation over prescaled fp8 H' (128B rows):
//   a[c] = (dc/16) * ( sum_{r in N(c)} H'[r] + H'[c] ) + bias
// Warp handles 4 nodes; lane = 4 features (4B load).
// 8 edges in flight per step (two independent 4-deep half2 trees) -> MLP 8.
// !FUSE_HEAD: out fp8 = relu(a)*16.  FUSE_HEAD: sigmoid head.
// ---------------------------------------------------------------------------
#define NPW 4

__device__ __forceinline__ void tree4_acc(uint32_t u0, uint32_t u1,
                                          uint32_t u2, uint32_t u3, float4& acc) {
    __half2 a0, b0, a1, b1, a2, b2, a3, b3;
    fp8x4_to_h2(u0, a0, b0);
    fp8x4_to_h2(u1, a1, b1);
    fp8x4_to_h2(u2, a2, b2);
    fp8x4_to_h2(u3, a3, b3);
    __half2 sa = __hadd2(__hadd2(a0, a1), __hadd2(a2, a3));
    __half2 sb = __hadd2(__hadd2(b0, b1), __hadd2(b2, b3));
    float2 fa = __half22float2(sa), fb = __half22float2(sb);
    acc.x += fa.x; acc.y += fa.y; acc.z += fb.x; acc.w += fb.y;
}

template <bool FUSE_HEAD>
__global__ void __launch_bounds__(256)
k_agg(const int* __restrict__ start, const int* __restrict__ srow,
      const float* __restrict__ dinv, const uint8_t* __restrict__ H8,
      const float* __restrict__ bias,
      const float* __restrict__ Wl, const float* __restrict__ bl,
      uint8_t* __restrict__ hout8, float* __restrict__ fout, int n) {
    const int lane = threadIdx.x & 31;
    const int warp = (blockIdx.x * blockDim.x + threadIdx.x) >> 5;
    int c0 = warp * NPW;
    if (c0 >= n) return;
    int c_end = min(c0 + NPW, n);

    float4 bv = __ldg((const float4*)bias + lane);
    float4 wv = make_float4(0.f, 0.f, 0.f, 0.f);
    float blv = 0.f;
    if (FUSE_HEAD) { wv = __ldg((const float4*)Wl + lane); blv = __ldg(bl); }

    for (int c = c0; c < c_end; c++) {
        int beg = __ldg(start + c);
        int end = __ldg(start + c + 1);
        float dc = __ldg(dinv + c) * (1.0f / FP8_SCALE);

        uint32_t su = __ldg((const uint32_t*)(H8 + (size_t)c * F) + lane);
        __half2 spa, spb; fp8x4_to_h2(su, spa, spb);
        float2 sfa = __half22float2(spa), sfb = __half22float2(spb);
        float4 acc = make_float4(sfa.x, sfa.y, sfb.x, sfb.y);

        for (int i = beg; i < end; i += 32) {
            int idx = i + lane;
            int rr = __ldg(srow + (idx < end ? idx : end - 1));
            int cnt = min(end - i, 32);
            int j = 0;
            for (; j + 8 <= cnt; j += 8) {
                int r0 = __shfl_sync(0xFFFFFFFFu, rr, j);
                int r1 = __shfl_sync(0xFFFFFFFFu, rr, j + 1);
                int r2 = __shfl_sync(0xFFFFFFFFu, rr, j + 2);
                int r3 = __shfl_sync(0xFFFFFFFFu, rr, j + 3);
                int r4 = __shfl_sync(0xFFFFFFFFu, rr, j + 4);
                int r5 = __shfl_sync(0xFFFFFFFFu, rr, j + 5);
                int r6 = __shfl_sync(0xFFFFFFFFu, rr, j + 6);
                int r7 = __shfl_sync(0xFFFFFFFFu, rr, j + 7);
                uint32_t u0 = __ldg((const uint32_t*)(H8 + (size_t)r0 * F) + lane);
                uint32_t u1 = __ldg((const uint32_t*)(H8 + (size_t)r1 * F) + lane);
                uint32_t u2 = __ldg((const uint32_t*)(H8 + (size_t)r2 * F) + lane);
                uint32_t u3 = __ldg((const uint32_t*)(H8 + (size_t)r3 * F) + lane);
                uint32_t u4 = __ldg((const uint32_t*)(H8 + (size_t)r4 * F) + lane);
                uint32_t u5 = __ldg((const uint32_t*)(H8 + (size_t)r5 * F) + lane);
                uint32_t u6 = __ldg((const uint32_t*)(H8 + (size_t)r6 * F) + lane);
                uint32_t u7 = __ldg((const uint32_t*)(H8 + (size_t)r7 * F) + lane);
                tree4_acc(u0, u1, u2, u3, acc);
                tree4_acc(u4, u5, u6, u7, acc);
            }
            for (; j + 4 <= cnt; j += 4) {
                int r0 = __shfl_sync(0xFFFFFFFFu, rr, j);
                int r1 = __shfl_sync(0xFFFFFFFFu, rr, j + 1);
                int r2 = __shfl_sync(0xFFFFFFFFu, rr, j + 2);
                int r3 = __shfl_sync(0xFFFFFFFFu, rr, j + 3);
                uint32_t u0 = __ldg((const uint32_t*)(H8 + (size_t)r0 * F) + lane);
                uint32_t u1 = __ldg((const uint32_t*)(H8 + (size_t)r1 * F) + lane);
                uint32_t u2 = __ldg((const uint32_t*)(H8 + (size_t)r2 * F) + lane);
                uint32_t u3 = __ldg((const uint32_t*)(H8 + (size_t)r3 * F) + lane);
                tree4_acc(u0, u1, u2, u3, acc);
            }
            for (; j < cnt; j++) {
                int r0 = __shfl_sync(0xFFFFFFFFu, rr, j);
                uint32_t u0 = __ldg((const uint32_t*)(H8 + (size_t)r0 * F) + lane);
                __half2 pa, pb; fp8x4_to_h2(u0, pa, pb);
                float2 fa = __half22float2(pa), fb = __half22float2(pb);
                acc.x += fa.x; acc.y += fa.y; acc.z += fb.x; acc.w += fb.y;
            }
        }

        float4 o = make_float4(fmaf(dc, acc.x, bv.x), fmaf(dc, acc.y, bv.y),
                               fmaf(dc, acc.z, bv.z), fmaf(dc, acc.w, bv.w));

        if (!FUSE_HEAD) {
            // relu, scale x16, store fp8
            o.x = fmaxf(o.x, 0.f) * FP8_SCALE; o.y = fmaxf(o.y, 0.f) * FP8_SCALE;
            o.z = fmaxf(o.z, 0.f) * FP8_SCALE; o.w = fmaxf(o.w, 0.f) * FP8_SCALE;
            uint32_t lo = f2_to_e4m3x2(o.x, o.y);
            uint32_t hi = f2_to_e4m3x2(o.z, o.w);
            *((uint32_t*)(hout8 + (size_t)c * F) + lane) = lo | (hi << 16);
        } else {
            float s = fmaxf(o.x, 0.f) * wv.x + fmaxf(o.y, 0.f) * wv.y +
                      fmaxf(o.z, 0.f) * wv.z + fmaxf(o.w, 0.f) * wv.w;
            #pragma unroll
            for (int off = 16; off; off >>= 1) s += __shfl_xor_sync(0xFFFFFFFFu, s, off);
            if (lane == 0) {
                float z = s + blv;
                fout[c] = 1.0f / (1.0f + expf(-z));
            }
        }
    }
}

// ---------------------------------------------------------------------------
extern "C" void kernel_launch(void* const* d_in, const int* in_sizes, int n_in,
                              void* d_out, int out_size) {
    const float* x  = (const float*)d_in[0];
    const int*   ei = (const int*)  d_in[1];
    const float* W1 = (const float*)d_in[2];
    const float* b1 = (const float*)d_in[3];
    const float* W2 = (const float*)d_in[4];
    const float* b2 = (const float*)d_in[5];
    const float* Wl = (const float*)d_in[6];
    const float* bl = (const float*)d_in[7];

    int n = in_sizes[0] / F;
    int E = in_sizes[1] / 2;
    const int* rowp = ei;
    const int* colp = ei + E;

    int *cnt, *start, *cursor, *bsum, *boff, *srow;
    float *dinv;
    uint8_t *h8, *a8;
    cudaGetSymbolAddress((void**)&cnt,    g_cnt);
    cudaGetSymbolAddress((void**)&start,  g_start);
    cudaGetSymbolAddress((void**)&cursor, g_cursor);
    cudaGetSymbolAddress((void**)&bsum,   g_bsum);
    cudaGetSymbolAddress((void**)&boff,   g_boff);
    cudaGetSymbolAddress((void**)&srow,   g_srow);
    cudaGetSymbolAddress((void**)&dinv,   g_dinv);
    cudaGetSymbolAddress((void**)&h8,     g_h8);
    cudaGetSymbolAddress((void**)&a8,     g_a8);

    const size_t gemm_smem = (size_t)(2 * 128 * SLD) * sizeof(bf16_t);
    cudaFuncSetAttribute((const void*)k_gemm_mma<float>,
                         cudaFuncAttributeMaxDynamicSharedMemorySize, (int)gemm_smem);
    cudaFuncSetAttribute((const void*)k_gemm_mma<uint8_t>,
                         cudaFuncAttributeMaxDynamicSharedMemorySize, (int)gemm_smem);

    // Side stream + events for overlapping the sort chain with GEMM1.
    static cudaStream_t s2 = nullptr;
    static cudaEvent_t evA = nullptr, evB = nullptr;
    static int init_tried = 0;
    if (!init_tried) {
        init_tried = 1;
        if (cudaStreamCreateWithFlags(&s2, cudaStreamNonBlocking) != cudaSuccess) s2 = nullptr;
        if (cudaEventCreateWithFlags(&evA, cudaEventDisableTiming) != cudaSuccess) evA = nullptr;
        if (cudaEventCreateWithFlags(&evB, cudaEventDisableTiming) != cudaSuccess) evB = nullptr;
    }
    bool par = (s2 != nullptr) && (evA != nullptr) && (evB != nullptr);

    int nb = (n + SCAN_BLK - 1) / SCAN_BLK;
    int gemm_grid = (n + 127) / 128;
    int agg_grid  = ((n + NPW - 1) / NPW * 32 + 255) / 256;

    // --- degree + dinv (cnt zeroed via memset node) ---
    cudaMemsetAsync(cnt, 0, (size_t)n * sizeof(int), 0);
    k_hist<<<(E + 255) / 256, 256>>>(colp, cnt, E);
    k_dinv<<<(n + 255) / 256, 256>>>(cnt, dinv, n);

    if (par) {
        cudaEventRecord(evA, 0);
        cudaStreamWaitEvent(s2, evA, 0);
        k_blocksum<<<nb, 256, 0, s2>>>(cnt, bsum, n);
        k_gemm_mma<float><<<gemm_grid, 256, gemm_smem>>>(x, W1, dinv, h8, FP8_SCALE, n);
        k_scanbsum  <<<1, 256, 0, s2>>>(bsum, boff, start, nb, n);
        k_writestart<<<nb, 256, 0, s2>>>(cnt, boff, start, cursor, n);
        k_scatter   <<<(E + 255) / 256, 256, 0, s2>>>(rowp, colp, cursor, srow, E);
        cudaEventRecord(evB, s2);
        cudaStreamWaitEvent(0, evB, 0);
    } else {
        k_blocksum  <<<nb, 256>>>(cnt, bsum, n);
        k_gemm_mma<float><<<gemm_grid, 256, gemm_smem>>>(x, W1, dinv, h8, FP8_SCALE, n);
        k_scanbsum  <<<1, 256>>>(bsum, boff, start, nb, n);
        k_writestart<<<nb, 256>>>(cnt, boff, start, cursor, n);
        k_scatter   <<<(E + 255) / 256, 256>>>(rowp, colp, cursor, srow, E);
    }

    // --- layer 1 agg (fp8 gather) -> fp8 a8 (x16) ---
    k_agg<false><<<agg_grid, 256>>>(start, srow, dinv, h8, b1, nullptr, nullptr, a8, nullptr, n);

    // --- layer 2: A carries x16 -> esc = 1.0 keeps H8 = 16*dinv*(a@W2) ---
    k_gemm_mma<uint8_t><<<gemm_grid, 256, gemm_smem>>>(a8, W2, dinv, h8, 1.0f, n);
    k_agg<true><<<agg_grid, 256>>>(start, srow, dinv, h8, b2, Wl, bl, nullptr, (float*)d_out, n);
}